// round 13
// baseline (speedup 1.0000x reference)
#include <cuda_runtime.h>
#include <cuda_fp16.h>
#include <cstdint>

#define DCH   512
#define HW    4096
#define NROWS 65536
#define KCB   1024
#define LOSS_OFF 33554432
#define PROB_OFF 33554433
#define WFLAG 1.5e-4f

// ---------------- device scratch ----------------
__device__ float g_cnorm[KCB];
__device__ float g_znorm[NROWS];
__device__ int   g_minidx[NROWS];
__device__ float g_partial[8192];
__device__ __half g_zhi[(size_t)NROWS * DCH];
__device__ __half g_zlo[(size_t)NROWS * DCH];
__device__ __half g_chi[(size_t)KCB * DCH];
__device__ __half g_sdist[(size_t)NROWS * KCB];   // approx dist - znorm, fp16
__device__ float g_cv[(size_t)NROWS * 24];        // per-nblk top-3 approx dist
__device__ int   g_ci[(size_t)NROWS * 24];        // matching code indices
__device__ int   g_list[NROWS];
__device__ int   g_count;

// ---------------- PTX helpers ----------------
__device__ __forceinline__ uint32_t smem_u32(const void* p) {
    uint32_t a;
    asm("{ .reg .u64 t; cvta.to.shared.u64 t, %1; cvt.u32.u64 %0, t; }" : "=r"(a) : "l"(p));
    return a;
}
__device__ __forceinline__ void cpasync16(uint32_t s, const void* g) {
    asm volatile("cp.async.cg.shared.global [%0], [%1], 16;" :: "r"(s), "l"(g));
}
#define CP_COMMIT()  asm volatile("cp.async.commit_group;" ::: "memory")
#define CP_WAIT0()   asm volatile("cp.async.wait_group 0;" ::: "memory")
#define CP_WAIT1()   asm volatile("cp.async.wait_group 1;" ::: "memory")

#define LDSM_X4(r0, r1, r2, r3, addr)                                          \
    asm volatile("ldmatrix.sync.aligned.m8n8.x4.shared.b16 {%0,%1,%2,%3}, [%4];" \
                 : "=r"(r0), "=r"(r1), "=r"(r2), "=r"(r3) : "r"(addr))

// non-volatile: ptxas may software-pipeline
#define MMA16816(d, a0, a1, a2, a3, b0, b1)                                    \
    asm("mma.sync.aligned.m16n8k16.row.col.f32.f16.f16.f32 "                   \
        "{%0,%1,%2,%3}, {%4,%5,%6,%7}, {%8,%9}, {%0,%1,%2,%3};"                \
        : "+f"((d)[0]), "+f"((d)[1]), "+f"((d)[2]), "+f"((d)[3])               \
        : "r"(a0), "r"(a1), "r"(a2), "r"(a3), "r"(b0), "r"(b1))

// lexicographic top-3 insert on (v1,j1,v2,j2,v3,j3)
#define INS3(dv, ji) do {                                                      \
    if ((dv) < v1 || ((dv) == v1 && (ji) < j1)) {                              \
        v3 = v2; j3 = j2; v2 = v1; j2 = j1; v1 = (dv); j1 = (ji);              \
    } else if ((dv) < v2 || ((dv) == v2 && (ji) < j2)) {                       \
        v3 = v2; j3 = j2; v2 = (dv); j2 = (ji);                                \
    } else if ((dv) < v3 || ((dv) == v3 && (ji) < j3)) {                       \
        v3 = (dv); j3 = (ji);                                                  \
    }                                                                          \
} while (0)

// ---------------------------------------------------------------------------
// codebook fp16 (hi only) + fused cnorm (sequential fp32) + counter zero
// ---------------------------------------------------------------------------
__global__ void k_csplit(const float* __restrict__ cb) {
    int idx = blockIdx.x * blockDim.x + threadIdx.x;
    if (idx == 0) g_count = 0;
    if (idx < (KCB * DCH) / 2) {
        float2 v = ((const float2*)cb)[idx];
        ((__half2*)g_chi)[idx] = __floats2half2_rn(v.x, v.y);
    }
    if (blockIdx.x < 4) {
        int jj = blockIdx.x * 256 + threadIdx.x;
        const float* r = cb + (size_t)jj * DCH;
        float acc = 0.f;
        for (int k = 0; k < DCH; ++k) {
            float v = r[k];
            acc = __fadd_rn(acc, __fmul_rn(v, v));
        }
        g_cnorm[jj] = acc;
    }
}

// ---------------------------------------------------------------------------
// z fp16 hi/lo split + fused znorm (exact sequential d-order per row)
// ---------------------------------------------------------------------------
__global__ __launch_bounds__(256)
void k_zsplit(const float* __restrict__ z) {
    __shared__ float sm[64 * 65];
    const int tid  = threadIdx.x;
    const int bi   = blockIdx.x >> 6;
    const int rem0 = (blockIdx.x & 63) << 6;
    const float* zb = z + (size_t)bi * (DCH * HW) + rem0;
    float zacc = 0.f;

    for (int kt = 0; kt < 8; ++kt) {
        __syncthreads();
        int k0 = kt * 64;
#pragma unroll
        for (int it = 0; it < 16; ++it) {
            int li = it * 256 + tid;
            int r = li & 63, k = li >> 6;
            sm[k * 65 + r] = zb[(size_t)(k0 + k) * HW + r];
        }
        __syncthreads();
        if (tid < 64) {
#pragma unroll 8
            for (int k = 0; k < 64; ++k) {
                float v = sm[k * 65 + tid];
                zacc = __fadd_rn(zacc, __fmul_rn(v, v));
            }
        }
        int r  = tid >> 2;
        int kq = tid & 3;
        uint32_t hbuf[8], lbuf[8];
#pragma unroll
        for (int i = 0; i < 8; ++i) {
            float v0 = sm[(kq * 16 + 2 * i)     * 65 + r];
            float v1 = sm[(kq * 16 + 2 * i + 1) * 65 + r];
            __half2 h = __floats2half2_rn(v0, v1);
            float h0 = __half2float(__low2half(h));
            float h1 = __half2float(__high2half(h));
            __half2 l = __floats2half2_rn(v0 - h0, v1 - h1);
            hbuf[i] = *(uint32_t*)&h;
            lbuf[i] = *(uint32_t*)&l;
        }
        size_t base = ((size_t)(bi * 4096 + rem0 + r)) * DCH + k0 + kq * 16;
        *(uint4*)((char*)g_zhi + base * 2)      = *(uint4*)(hbuf);
        *(uint4*)((char*)g_zhi + base * 2 + 16) = *(uint4*)(hbuf + 4);
        *(uint4*)((char*)g_zlo + base * 2)      = *(uint4*)(lbuf);
        *(uint4*)((char*)g_zlo + base * 2 + 16) = *(uint4*)(lbuf + 4);
    }
    if (tid < 64) g_znorm[bi * 4096 + rem0 + tid] = zacc;
}

// ---------------------------------------------------------------------------
// HMMA GEMM: fp16 2-product split, CTA 128x128, K-chunk 32, 2 CTAs/SM,
// 3-stage cp.async ring (wait_group 1 -> 2 compute periods of load slack).
// Epilogue: per-nblk top-3 exact-fp32 candidates + fp16 (dist - zn) store.
// ---------------------------------------------------------------------------
#define PITCH 80
#define T_A_HI 0
#define T_A_LO 10240
#define T_B_HI 20480
#define STAGE_BYTES 30720
#define S_CN  92160
#define S_ZN  92672
#define S_CV  93184
#define S_CI  96256
#define GEMM_SMEM 99328

__global__ __launch_bounds__(256, 2)
void k_gemm() {
    extern __shared__ char smem[];
    const uint32_t sb = smem_u32(smem);
    const int tid   = threadIdx.x;
    const int lane  = tid & 31;
    const int wid   = tid >> 5;
    const int wm    = wid & 3;
    const int wn    = wid >> 2;
    const int rowblk = blockIdx.x >> 3;
    const int nblk   = blockIdx.x & 7;
    const int row0   = rowblk << 7;
    const int n0     = nblk << 7;

    const int srow = tid >> 2;
    const int sch  = tid & 3;

    const char* gAh = (const char*)g_zhi + ((size_t)(row0 + srow) << 10) + sch * 16;
    const char* gAl = (const char*)g_zlo + ((size_t)(row0 + srow) << 10) + sch * 16;
    const char* gBh = (const char*)g_chi + ((size_t)(n0   + srow) << 10) + sch * 16;
    const uint32_t sOff = srow * PITCH + sch * 16;

#define LOAD_STAGE(stg, kc) do {                                               \
    uint32_t s0 = sb + (stg) * STAGE_BYTES + sOff;                             \
    size_t   go = (size_t)(kc) * 64;                                           \
    cpasync16(s0 + T_A_HI,              gAh + go);                             \
    cpasync16(s0 + T_A_HI + 64 * PITCH, gAh + go + (size_t)64 * 1024);         \
    cpasync16(s0 + T_A_LO,              gAl + go);                             \
    cpasync16(s0 + T_A_LO + 64 * PITCH, gAl + go + (size_t)64 * 1024);         \
    cpasync16(s0 + T_B_HI,              gBh + go);                             \
    cpasync16(s0 + T_B_HI + 64 * PITCH, gBh + go + (size_t)64 * 1024);         \
    CP_COMMIT();                                                               \
} while (0)

    LOAD_STAGE(0, 0);
    LOAD_STAGE(1, 1);

    float* s_cn = (float*)(smem + S_CN);
    float* s_zn = (float*)(smem + S_ZN);
    if (tid < 128) {
        s_cn[tid] = g_cnorm[n0 + tid];
        s_zn[tid] = g_znorm[row0 + tid];
    }

    float acc[2][8][4];
#pragma unroll
    for (int mi = 0; mi < 2; ++mi)
#pragma unroll
        for (int n8 = 0; n8 < 8; ++n8)
#pragma unroll
            for (int e = 0; e < 4; ++e) acc[mi][n8][e] = 0.f;

    const int aRow = (lane & 15);
    const int aChk = (lane >> 4);
    const int bRow = (lane & 7) + ((lane >> 4) << 3);
    const int bChk = ((lane >> 3) & 1);

    int stg = 0;
    for (int kc = 0; kc < 16; ++kc) {
        // stage kc must be resident; with ring depth 3, allow 1 newer pending
        if (kc < 15) { CP_WAIT1(); } else { CP_WAIT0(); }
        __syncthreads();   // also: all warps done with stage (kc-1)%3
        if (kc + 2 < 16) {
            int nstg = stg + 2; if (nstg >= 3) nstg -= 3;
            LOAD_STAGE(nstg, kc + 2);
        }

        const uint32_t st = sb + stg * STAGE_BYTES;
        if (++stg == 3) stg = 0;
#pragma unroll
        for (int ks = 0; ks < 2; ++ks) {
            uint32_t ah[2][4], al[2][4];
#pragma unroll
            for (int mi = 0; mi < 2; ++mi) {
                uint32_t ad = st + (wm * 32 + mi * 16 + aRow) * PITCH
                            + (ks * 2 + aChk) * 16;
                LDSM_X4(ah[mi][0], ah[mi][1], ah[mi][2], ah[mi][3], ad + T_A_HI);
                LDSM_X4(al[mi][0], al[mi][1], al[mi][2], al[mi][3], ad + T_A_LO);
            }
#pragma unroll
            for (int gp = 0; gp < 2; ++gp) {
                const int g0 = 2 * gp, g1 = 2 * gp + 1;
                uint32_t b0h[4], b1h[4];
                uint32_t bd0 = st + (wn * 64 + g0 * 16 + bRow) * PITCH
                             + (ks * 2 + bChk) * 16 + T_B_HI;
                uint32_t bd1 = st + (wn * 64 + g1 * 16 + bRow) * PITCH
                             + (ks * 2 + bChk) * 16 + T_B_HI;
                LDSM_X4(b0h[0], b0h[1], b0h[2], b0h[3], bd0);
                LDSM_X4(b1h[0], b1h[1], b1h[2], b1h[3], bd1);

                // term hh (8 distinct accumulators)
                MMA16816(acc[0][2*g0],   ah[0][0],ah[0][1],ah[0][2],ah[0][3], b0h[0], b0h[1]);
                MMA16816(acc[0][2*g0+1], ah[0][0],ah[0][1],ah[0][2],ah[0][3], b0h[2], b0h[3]);
                MMA16816(acc[1][2*g0],   ah[1][0],ah[1][1],ah[1][2],ah[1][3], b0h[0], b0h[1]);
                MMA16816(acc[1][2*g0+1], ah[1][0],ah[1][1],ah[1][2],ah[1][3], b0h[2], b0h[3]);
                MMA16816(acc[0][2*g1],   ah[0][0],ah[0][1],ah[0][2],ah[0][3], b1h[0], b1h[1]);
                MMA16816(acc[0][2*g1+1], ah[0][0],ah[0][1],ah[0][2],ah[0][3], b1h[2], b1h[3]);
                MMA16816(acc[1][2*g1],   ah[1][0],ah[1][1],ah[1][2],ah[1][3], b1h[0], b1h[1]);
                MMA16816(acc[1][2*g1+1], ah[1][0],ah[1][1],ah[1][2],ah[1][3], b1h[2], b1h[3]);
                // term lh (same B fragments)
                MMA16816(acc[0][2*g0],   al[0][0],al[0][1],al[0][2],al[0][3], b0h[0], b0h[1]);
                MMA16816(acc[0][2*g0+1], al[0][0],al[0][1],al[0][2],al[0][3], b0h[2], b0h[3]);
                MMA16816(acc[1][2*g0],   al[1][0],al[1][1],al[1][2],al[1][3], b0h[0], b0h[1]);
                MMA16816(acc[1][2*g0+1], al[1][0],al[1][1],al[1][2],al[1][3], b0h[2], b0h[3]);
                MMA16816(acc[0][2*g1],   al[0][0],al[0][1],al[0][2],al[0][3], b1h[0], b1h[1]);
                MMA16816(acc[0][2*g1+1], al[0][0],al[0][1],al[0][2],al[0][3], b1h[2], b1h[3]);
                MMA16816(acc[1][2*g1],   al[1][0],al[1][1],al[1][2],al[1][3], b1h[0], b1h[1]);
                MMA16816(acc[1][2*g1+1], al[1][0],al[1][1],al[1][2],al[1][3], b1h[2], b1h[3]);
            }
        }
    }
#undef LOAD_STAGE

    // epilogue: exact fp32 dist -> top-3 candidates; fp16 (dist - zn) store
    float* svv = (float*)(smem + S_CV);
    int*   sii = (int*)(smem + S_CI);
#pragma unroll
    for (int mi = 0; mi < 2; ++mi) {
        const int rbase = wm * 32 + mi * 16 + (lane >> 2);
#pragma unroll
        for (int h = 0; h < 2; ++h) {
            const int row = rbase + 8 * h;
            const float zn = s_zn[row];
            float v1 = 3.4e38f, v2 = 3.4e38f, v3 = 3.4e38f;
            int   j1 = 0x7fffffff, j2 = 0x7fffffff, j3 = 0x7fffffff;
#pragma unroll
            for (int n8 = 0; n8 < 8; ++n8) {
                int cloc = wn * 64 + n8 * 8 + (lane & 3) * 2;
                float cn0 = s_cn[cloc], cn1 = s_cn[cloc + 1];
                float* a = acc[mi][n8];
                float d0 = __fadd_rn(__fadd_rn(zn, cn0), __fmul_rn(-2.f, a[2 * h]));
                float d1 = __fadd_rn(__fadd_rn(zn, cn1), __fmul_rn(-2.f, a[2 * h + 1]));
                int j = n0 + cloc;
                INS3(d0, j);
                INS3(d1, j + 1);
                __half2 hs = __floats2half2_rn(d0 - zn, d1 - zn);
                *(__half2*)((char*)g_sdist + (((size_t)(row0 + row) << 10) + j) * 2) = hs;
            }
#pragma unroll
            for (int off = 1; off <= 2; off <<= 1) {
                float ov1 = __shfl_xor_sync(0xffffffff, v1, off);
                int   oj1 = __shfl_xor_sync(0xffffffff, j1, off);
                float ov2 = __shfl_xor_sync(0xffffffff, v2, off);
                int   oj2 = __shfl_xor_sync(0xffffffff, j2, off);
                float ov3 = __shfl_xor_sync(0xffffffff, v3, off);
                int   oj3 = __shfl_xor_sync(0xffffffff, j3, off);
                INS3(ov1, oj1);
                INS3(ov2, oj2);
                INS3(ov3, oj3);
            }
            if ((lane & 3) == 0) {
                int b = (wn * 128 + row) * 3;
                svv[b] = v1; svv[b + 1] = v2; svv[b + 2] = v3;
                sii[b] = j1; sii[b + 1] = j2; sii[b + 2] = j3;
            }
        }
    }
    __syncthreads();
    if (tid < 128) {
        int b0 = tid * 3, b1 = (128 + tid) * 3;
        float v1 = svv[b0], v2 = svv[b0 + 1], v3 = svv[b0 + 2];
        int   j1 = sii[b0], j2 = sii[b0 + 1], j3 = sii[b0 + 2];
        float w1 = svv[b1], w2 = svv[b1 + 1], w3 = svv[b1 + 2];
        int   k1 = sii[b1], k2 = sii[b1 + 1], k3 = sii[b1 + 2];
        INS3(w1, k1);
        INS3(w2, k2);
        INS3(w3, k3);
        size_t g = ((size_t)(row0 + tid) * 8 + nblk) * 3;
        g_cv[g] = v1; g_cv[g + 1] = v2; g_cv[g + 2] = v3;
        g_ci[g] = j1; g_ci[g + 1] = j2; g_ci[g + 2] = j3;
    }
}

// ---------------------------------------------------------------------------
// k_amin: reduce 24 candidates/row -> approx argmin; flag near-ties for refine
// ---------------------------------------------------------------------------
__global__ __launch_bounds__(256)
void k_amin() {
    int row = blockIdx.x * 256 + threadIdx.x;
    const float* cv = g_cv + (size_t)row * 24;
    const int*   ci = g_ci + (size_t)row * 24;
    float v1 = 3.4e38f, v2 = 3.4e38f;
    int i1 = 0x7fffffff;
#pragma unroll
    for (int k = 0; k < 24; ++k) {
        float v = cv[k];
        int   i = ci[k];
        if (v < v1 || (v == v1 && i < i1)) { v2 = v1; v1 = v; i1 = i; }
        else if (v < v2) v2 = v;
    }
    g_minidx[row] = i1;
    if (v2 - v1 <= WFLAG) {
        int p = atomicAdd(&g_count, 1);
        g_list[p] = row;
    }
}

// ---------------------------------------------------------------------------
// k_refine: exact fp32 dist for all within-window candidates of flagged rows
// ---------------------------------------------------------------------------
__global__ __launch_bounds__(128)
void k_refine(const float* __restrict__ z, const float* __restrict__ cb) {
    __shared__ float zrow[512];
    __shared__ float cdist[24];
    const int tid  = threadIdx.x;
    const int lane = tid & 31;
    const int w    = tid >> 5;
    const int cnt  = g_count;

    for (int b = blockIdx.x; b < cnt; b += gridDim.x) {
        __syncthreads();
        const int row = g_list[b];
        const int bi  = row >> 12;
        const int rem = row & 4095;
        for (int d = tid; d < 512; d += 128)
            zrow[d] = z[(size_t)bi * (DCH * HW) + (size_t)d * HW + rem];
        if (tid < 24) cdist[tid] = 3.4e38f;
        __syncthreads();

        const float* cv = g_cv + (size_t)row * 24;
        const int*   ci = g_ci + (size_t)row * 24;
        float v1 = 3.4e38f;
#pragma unroll
        for (int k = 0; k < 24; ++k) v1 = fminf(v1, cv[k]);
        const float zn = g_znorm[row];

        for (int c = w; c < 24; c += 4) {
            if (cv[c] <= v1 + WFLAG) {
                int idx = ci[c];
                const float* cr = cb + (size_t)idx * DCH;
                float dot = 0.f;
#pragma unroll
                for (int t = 0; t < 16; ++t)
                    dot = fmaf(zrow[lane + 32 * t], cr[lane + 32 * t], dot);
#pragma unroll
                for (int off = 16; off > 0; off >>= 1)
                    dot += __shfl_xor_sync(0xffffffff, dot, off);
                if (lane == 0)
                    cdist[c] = __fadd_rn(__fadd_rn(zn, g_cnorm[idx]),
                                         __fmul_rn(-2.f, dot));
            }
        }
        __syncthreads();
        if (tid == 0) {
            float bv = 3.4e38f;
            int bidx = 0x7fffffff;
#pragma unroll
            for (int k = 0; k < 24; ++k) {
                if (cdist[k] < 3.3e38f) {
                    int ii = ci[k];
                    if (cdist[k] < bv || (cdist[k] == bv && ii < bidx)) {
                        bv = cdist[k]; bidx = ii;
                    }
                }
            }
            g_minidx[row] = bidx;
        }
    }
}

// ---------------------------------------------------------------------------
// k_prob: softmax over fp16 shifted dist (shift-invariant; argmin elsewhere)
// ---------------------------------------------------------------------------
__global__ __launch_bounds__(256)
void k_prob(float* __restrict__ prob) {
    __shared__ float sval[4][64];
    const int tid = threadIdx.x;
    const int rg  = tid >> 6;
    const int cl  = tid & 63;
    const int row = (blockIdx.x << 2) + rg;
    const size_t base = ((size_t)row << 10) + cl;

    float s[16];
    float mv = 3.4e38f;
#pragma unroll
    for (int i = 0; i < 16; ++i) {
        s[i] = __half2float(g_sdist[base + 64 * i]);
        if (s[i] < mv) mv = s[i];
    }
    sval[rg][cl] = mv;
    __syncthreads();
    for (int off = 32; off > 0; off >>= 1) {
        if (cl < off) {
            float v2 = sval[rg][cl + off];
            if (v2 < sval[rg][cl]) sval[rg][cl] = v2;
        }
        __syncthreads();
    }
    float m = sval[rg][0];
    __syncthreads();

    float e[16], ssum = 0.f;
#pragma unroll
    for (int i = 0; i < 16; ++i) {
        e[i] = __expf(__fmul_rn(-2.f, __fsub_rn(s[i], m)));
        ssum += e[i];
    }
    sval[rg][cl] = ssum;
    __syncthreads();
    for (int off = 32; off > 0; off >>= 1) {
        if (cl < off) sval[rg][cl] += sval[rg][cl + off];
        __syncthreads();
    }
    float invS = 1.0f / sval[rg][0];
    float* op = prob + base;
#pragma unroll
    for (int i = 0; i < 16; ++i)
        op[64 * i] = e[i] * invS;
}

// ---------------------------------------------------------------------------
// gather z_q + loss partials: 8192 blocks x (32 rows, 128-d chunk)
// ---------------------------------------------------------------------------
__global__ __launch_bounds__(256, 6)
void k_gather(const float* __restrict__ z,
              const float* __restrict__ cb,
              float* __restrict__ outzq) {
    __shared__ float cbuf[128 * 33];
    __shared__ int   s_idx[32];
    __shared__ float sred[256];
    const int tid   = threadIdx.x;
    const int row0  = (blockIdx.x >> 2) << 5;
    const int dbase = (blockIdx.x & 3) << 7;
    const int bi    = row0 >> 12;
    const int rem0  = row0 & 4095;
    if (tid < 32) s_idx[tid] = g_minidx[row0 + tid];
    __syncthreads();

#pragma unroll
    for (int i = tid; i < 4096; i += 256) {
        int r = i >> 7, c = i & 127;
        cbuf[c * 33 + r] = cb[(size_t)s_idx[r] * DCH + dbase + c];
    }
    __syncthreads();

    float lsum = 0.f;
    const size_t zb = (size_t)bi * (DCH * HW) + rem0;
#pragma unroll
    for (int it = 0; it < 16; ++it) {
        int l    = tid + (it << 8);
        int rloc = l & 31;
        int dloc = l >> 5;
        size_t gi = zb + (size_t)(dbase + dloc) * HW + rloc;
        float c  = cbuf[dloc * 33 + rloc];
        float zv = z[gi];
        float df = c - zv;
        lsum += df * df;
        outzq[gi] = c;
    }
    sred[tid] = lsum;
    __syncthreads();
    for (int off = 128; off > 0; off >>= 1) {
        if (tid < off) sred[tid] += sred[tid + off];
        __syncthreads();
    }
    if (tid == 0) g_partial[blockIdx.x] = sred[0];
}

__global__ void k_loss(float* __restrict__ out) {
    __shared__ float s[1024];
    int tid = threadIdx.x;
    float a = 0.f;
#pragma unroll
    for (int i = 0; i < 8; ++i) a += g_partial[tid + 1024 * i];
    s[tid] = a;
    __syncthreads();
    for (int off = 512; off > 0; off >>= 1) {
        if (tid < off) s[tid] += s[tid + off];
        __syncthreads();
    }
    if (tid == 0) out[0] = s[0] * (1.25f / 33554432.f);
}

// ---------------------------------------------------------------------------
extern "C" void kernel_launch(void* const* d_in, const int* in_sizes, int n_in,
                              void* d_out, int out_size) {
    const float* z  = (const float*)d_in[0];
    const float* cb = (const float*)d_in[1];
    float* out = (float*)d_out;

    cudaFuncSetAttribute(k_gemm, cudaFuncAttributeMaxDynamicSharedMemorySize, GEMM_SMEM);

    k_csplit<<<1024, 256>>>(cb);
    k_zsplit<<<1024, 256>>>(z);
    k_gemm<<<4096, 256, GEMM_SMEM>>>();
    k_amin<<<256, 256>>>();
    k_refine<<<2048, 128>>>(z, cb);
    k_prob<<<16384, 256>>>(out + PROB_OFF);
    k_gather<<<8192, 256>>>(z, cb, out);
    k_loss<<<1, 1024>>>(out + LOSS_OFF);
}

// round 14
// speedup vs baseline: 1.0210x; 1.0210x over previous
#include <cuda_runtime.h>
#include <cuda_fp16.h>
#include <cstdint>

#define DCH   512
#define HW    4096
#define NROWS 65536
#define KCB   1024
#define LOSS_OFF 33554432
#define PROB_OFF 33554433
#define WFLAG 1.5e-4f

// ---------------- device scratch ----------------
__device__ float g_cnorm[KCB];
__device__ float g_znorm[NROWS];
__device__ int   g_minidx[NROWS];
__device__ float g_partial[8192];
__device__ __half g_zhi[(size_t)NROWS * DCH];
__device__ __half g_zlo[(size_t)NROWS * DCH];
__device__ __half g_chi[(size_t)KCB * DCH];
__device__ __half g_sdist[(size_t)NROWS * KCB];   // approx dist - znorm, fp16
__device__ float g_cv[(size_t)NROWS * 24];        // per-nblk top-3 approx dist
__device__ int   g_ci[(size_t)NROWS * 24];        // matching code indices
__device__ int   g_list[NROWS];
__device__ int   g_count;

// ---------------- PTX helpers ----------------
__device__ __forceinline__ uint32_t smem_u32(const void* p) {
    uint32_t a;
    asm("{ .reg .u64 t; cvta.to.shared.u64 t, %1; cvt.u32.u64 %0, t; }" : "=r"(a) : "l"(p));
    return a;
}
__device__ __forceinline__ void cpasync16(uint32_t s, const void* g) {
    asm volatile("cp.async.cg.shared.global [%0], [%1], 16;" :: "r"(s), "l"(g));
}
#define CP_COMMIT()  asm volatile("cp.async.commit_group;" ::: "memory")
#define CP_WAIT0()   asm volatile("cp.async.wait_group 0;" ::: "memory")

#define LDSM_X4(r0, r1, r2, r3, addr)                                          \
    asm volatile("ldmatrix.sync.aligned.m8n8.x4.shared.b16 {%0,%1,%2,%3}, [%4];" \
                 : "=r"(r0), "=r"(r1), "=r"(r2), "=r"(r3) : "r"(addr))

// non-volatile: ptxas may software-pipeline
#define MMA16816(d, a0, a1, a2, a3, b0, b1)                                    \
    asm("mma.sync.aligned.m16n8k16.row.col.f32.f16.f16.f32 "                   \
        "{%0,%1,%2,%3}, {%4,%5,%6,%7}, {%8,%9}, {%0,%1,%2,%3};"                \
        : "+f"((d)[0]), "+f"((d)[1]), "+f"((d)[2]), "+f"((d)[3])               \
        : "r"(a0), "r"(a1), "r"(a2), "r"(a3), "r"(b0), "r"(b1))

// lexicographic top-3 insert on (v1,j1,v2,j2,v3,j3)
#define INS3(dv, ji) do {                                                      \
    if ((dv) < v1 || ((dv) == v1 && (ji) < j1)) {                              \
        v3 = v2; j3 = j2; v2 = v1; j2 = j1; v1 = (dv); j1 = (ji);              \
    } else if ((dv) < v2 || ((dv) == v2 && (ji) < j2)) {                       \
        v3 = v2; j3 = j2; v2 = (dv); j2 = (ji);                                \
    } else if ((dv) < v3 || ((dv) == v3 && (ji) < j3)) {                       \
        v3 = (dv); j3 = (ji);                                                  \
    }                                                                          \
} while (0)

// ---------------------------------------------------------------------------
// codebook fp16 (hi only) + fused cnorm (sequential fp32) + counter zero
// ---------------------------------------------------------------------------
__global__ void k_csplit(const float* __restrict__ cb) {
    int idx = blockIdx.x * blockDim.x + threadIdx.x;
    if (idx == 0) g_count = 0;
    if (idx < (KCB * DCH) / 2) {
        float2 v = ((const float2*)cb)[idx];
        ((__half2*)g_chi)[idx] = __floats2half2_rn(v.x, v.y);
    }
    if (blockIdx.x < 4) {
        int jj = blockIdx.x * 256 + threadIdx.x;
        const float* r = cb + (size_t)jj * DCH;
        float acc = 0.f;
        for (int k = 0; k < DCH; ++k) {
            float v = r[k];
            acc = __fadd_rn(acc, __fmul_rn(v, v));
        }
        g_cnorm[jj] = acc;
    }
}

// ---------------------------------------------------------------------------
// z fp16 hi/lo split + fused znorm (exact sequential d-order per row)
// ---------------------------------------------------------------------------
__global__ __launch_bounds__(256)
void k_zsplit(const float* __restrict__ z) {
    __shared__ float sm[64 * 65];
    const int tid  = threadIdx.x;
    const int bi   = blockIdx.x >> 6;
    const int rem0 = (blockIdx.x & 63) << 6;
    const float* zb = z + (size_t)bi * (DCH * HW) + rem0;
    float zacc = 0.f;

    for (int kt = 0; kt < 8; ++kt) {
        __syncthreads();
        int k0 = kt * 64;
#pragma unroll
        for (int it = 0; it < 16; ++it) {
            int li = it * 256 + tid;
            int r = li & 63, k = li >> 6;
            sm[k * 65 + r] = zb[(size_t)(k0 + k) * HW + r];
        }
        __syncthreads();
        if (tid < 64) {
#pragma unroll 8
            for (int k = 0; k < 64; ++k) {
                float v = sm[k * 65 + tid];
                zacc = __fadd_rn(zacc, __fmul_rn(v, v));
            }
        }
        int r  = tid >> 2;
        int kq = tid & 3;
        uint32_t hbuf[8], lbuf[8];
#pragma unroll
        for (int i = 0; i < 8; ++i) {
            float v0 = sm[(kq * 16 + 2 * i)     * 65 + r];
            float v1 = sm[(kq * 16 + 2 * i + 1) * 65 + r];
            __half2 h = __floats2half2_rn(v0, v1);
            float h0 = __half2float(__low2half(h));
            float h1 = __half2float(__high2half(h));
            __half2 l = __floats2half2_rn(v0 - h0, v1 - h1);
            hbuf[i] = *(uint32_t*)&h;
            lbuf[i] = *(uint32_t*)&l;
        }
        size_t base = ((size_t)(bi * 4096 + rem0 + r)) * DCH + k0 + kq * 16;
        *(uint4*)((char*)g_zhi + base * 2)      = *(uint4*)(hbuf);
        *(uint4*)((char*)g_zhi + base * 2 + 16) = *(uint4*)(hbuf + 4);
        *(uint4*)((char*)g_zlo + base * 2)      = *(uint4*)(lbuf);
        *(uint4*)((char*)g_zlo + base * 2 + 16) = *(uint4*)(lbuf + 4);
    }
    if (tid < 64) g_znorm[bi * 4096 + rem0 + tid] = zacc;
}

// ---------------------------------------------------------------------------
// HMMA GEMM (round-10 proven config): fp16 2-product split, CTA 128x128,
// K-chunk 32, double buffer, 2 CTAs/SM, one barrier per k-chunk.
// Epilogue: per-nblk top-3 exact-fp32 candidates + fp16 (dist - zn) store.
// ---------------------------------------------------------------------------
#define PITCH 80
#define T_A_HI 0
#define T_A_LO 10240
#define T_B_HI 20480
#define STAGE_BYTES 30720
#define S_CN  61440
#define S_ZN  61952
#define S_CV  62464
#define S_CI  65536
#define GEMM_SMEM 68608

__global__ __launch_bounds__(256, 2)
void k_gemm() {
    extern __shared__ char smem[];
    const uint32_t sb = smem_u32(smem);
    const int tid   = threadIdx.x;
    const int lane  = tid & 31;
    const int wid   = tid >> 5;
    const int wm    = wid & 3;
    const int wn    = wid >> 2;
    const int rowblk = blockIdx.x >> 3;
    const int nblk   = blockIdx.x & 7;
    const int row0   = rowblk << 7;
    const int n0     = nblk << 7;

    const int srow = tid >> 2;
    const int sch  = tid & 3;

    const char* gAh = (const char*)g_zhi + ((size_t)(row0 + srow) << 10) + sch * 16;
    const char* gAl = (const char*)g_zlo + ((size_t)(row0 + srow) << 10) + sch * 16;
    const char* gBh = (const char*)g_chi + ((size_t)(n0   + srow) << 10) + sch * 16;
    const uint32_t sOff = srow * PITCH + sch * 16;

#define LOAD_STAGE(stg, kc) do {                                               \
    uint32_t s0 = sb + (stg) * STAGE_BYTES + sOff;                             \
    size_t   go = (size_t)(kc) * 64;                                           \
    cpasync16(s0 + T_A_HI,              gAh + go);                             \
    cpasync16(s0 + T_A_HI + 64 * PITCH, gAh + go + (size_t)64 * 1024);         \
    cpasync16(s0 + T_A_LO,              gAl + go);                             \
    cpasync16(s0 + T_A_LO + 64 * PITCH, gAl + go + (size_t)64 * 1024);         \
    cpasync16(s0 + T_B_HI,              gBh + go);                             \
    cpasync16(s0 + T_B_HI + 64 * PITCH, gBh + go + (size_t)64 * 1024);         \
    CP_COMMIT();                                                               \
} while (0)

    LOAD_STAGE(0, 0);

    float* s_cn = (float*)(smem + S_CN);
    float* s_zn = (float*)(smem + S_ZN);
    if (tid < 128) {
        s_cn[tid] = g_cnorm[n0 + tid];
        s_zn[tid] = g_znorm[row0 + tid];
    }

    float acc[2][8][4];
#pragma unroll
    for (int mi = 0; mi < 2; ++mi)
#pragma unroll
        for (int n8 = 0; n8 < 8; ++n8)
#pragma unroll
            for (int e = 0; e < 4; ++e) acc[mi][n8][e] = 0.f;

    const int aRow = (lane & 15);
    const int aChk = (lane >> 4);
    const int bRow = (lane & 7) + ((lane >> 4) << 3);
    const int bChk = ((lane >> 3) & 1);

    for (int kc = 0; kc < 16; ++kc) {
        CP_WAIT0();
        __syncthreads();
        if (kc + 1 < 16) LOAD_STAGE((kc + 1) & 1, kc + 1);

        const uint32_t st = sb + (kc & 1) * STAGE_BYTES;
#pragma unroll
        for (int ks = 0; ks < 2; ++ks) {
            uint32_t ah[2][4], al[2][4];
#pragma unroll
            for (int mi = 0; mi < 2; ++mi) {
                uint32_t ad = st + (wm * 32 + mi * 16 + aRow) * PITCH
                            + (ks * 2 + aChk) * 16;
                LDSM_X4(ah[mi][0], ah[mi][1], ah[mi][2], ah[mi][3], ad + T_A_HI);
                LDSM_X4(al[mi][0], al[mi][1], al[mi][2], al[mi][3], ad + T_A_LO);
            }
#pragma unroll
            for (int gp = 0; gp < 2; ++gp) {
                const int g0 = 2 * gp, g1 = 2 * gp + 1;
                uint32_t b0h[4], b1h[4];
                uint32_t bd0 = st + (wn * 64 + g0 * 16 + bRow) * PITCH
                             + (ks * 2 + bChk) * 16 + T_B_HI;
                uint32_t bd1 = st + (wn * 64 + g1 * 16 + bRow) * PITCH
                             + (ks * 2 + bChk) * 16 + T_B_HI;
                LDSM_X4(b0h[0], b0h[1], b0h[2], b0h[3], bd0);
                LDSM_X4(b1h[0], b1h[1], b1h[2], b1h[3], bd1);

                // term hh (8 distinct accumulators)
                MMA16816(acc[0][2*g0],   ah[0][0],ah[0][1],ah[0][2],ah[0][3], b0h[0], b0h[1]);
                MMA16816(acc[0][2*g0+1], ah[0][0],ah[0][1],ah[0][2],ah[0][3], b0h[2], b0h[3]);
                MMA16816(acc[1][2*g0],   ah[1][0],ah[1][1],ah[1][2],ah[1][3], b0h[0], b0h[1]);
                MMA16816(acc[1][2*g0+1], ah[1][0],ah[1][1],ah[1][2],ah[1][3], b0h[2], b0h[3]);
                MMA16816(acc[0][2*g1],   ah[0][0],ah[0][1],ah[0][2],ah[0][3], b1h[0], b1h[1]);
                MMA16816(acc[0][2*g1+1], ah[0][0],ah[0][1],ah[0][2],ah[0][3], b1h[2], b1h[3]);
                MMA16816(acc[1][2*g1],   ah[1][0],ah[1][1],ah[1][2],ah[1][3], b1h[0], b1h[1]);
                MMA16816(acc[1][2*g1+1], ah[1][0],ah[1][1],ah[1][2],ah[1][3], b1h[2], b1h[3]);
                // term lh (same B fragments)
                MMA16816(acc[0][2*g0],   al[0][0],al[0][1],al[0][2],al[0][3], b0h[0], b0h[1]);
                MMA16816(acc[0][2*g0+1], al[0][0],al[0][1],al[0][2],al[0][3], b0h[2], b0h[3]);
                MMA16816(acc[1][2*g0],   al[1][0],al[1][1],al[1][2],al[1][3], b0h[0], b0h[1]);
                MMA16816(acc[1][2*g0+1], al[1][0],al[1][1],al[1][2],al[1][3], b0h[2], b0h[3]);
                MMA16816(acc[0][2*g1],   al[0][0],al[0][1],al[0][2],al[0][3], b1h[0], b1h[1]);
                MMA16816(acc[0][2*g1+1], al[0][0],al[0][1],al[0][2],al[0][3], b1h[2], b1h[3]);
                MMA16816(acc[1][2*g1],   al[1][0],al[1][1],al[1][2],al[1][3], b1h[0], b1h[1]);
                MMA16816(acc[1][2*g1+1], al[1][0],al[1][1],al[1][2],al[1][3], b1h[2], b1h[3]);
            }
        }
    }
#undef LOAD_STAGE

    // epilogue: exact fp32 dist -> top-3 candidates; fp16 (dist - zn) store
    float* svv = (float*)(smem + S_CV);
    int*   sii = (int*)(smem + S_CI);
#pragma unroll
    for (int mi = 0; mi < 2; ++mi) {
        const int rbase = wm * 32 + mi * 16 + (lane >> 2);
#pragma unroll
        for (int h = 0; h < 2; ++h) {
            const int row = rbase + 8 * h;
            const float zn = s_zn[row];
            float v1 = 3.4e38f, v2 = 3.4e38f, v3 = 3.4e38f;
            int   j1 = 0x7fffffff, j2 = 0x7fffffff, j3 = 0x7fffffff;
#pragma unroll
            for (int n8 = 0; n8 < 8; ++n8) {
                int cloc = wn * 64 + n8 * 8 + (lane & 3) * 2;
                float cn0 = s_cn[cloc], cn1 = s_cn[cloc + 1];
                float* a = acc[mi][n8];
                float d0 = __fadd_rn(__fadd_rn(zn, cn0), __fmul_rn(-2.f, a[2 * h]));
                float d1 = __fadd_rn(__fadd_rn(zn, cn1), __fmul_rn(-2.f, a[2 * h + 1]));
                int j = n0 + cloc;
                INS3(d0, j);
                INS3(d1, j + 1);
                __half2 hs = __floats2half2_rn(d0 - zn, d1 - zn);
                *(__half2*)((char*)g_sdist + (((size_t)(row0 + row) << 10) + j) * 2) = hs;
            }
#pragma unroll
            for (int off = 1; off <= 2; off <<= 1) {
                float ov1 = __shfl_xor_sync(0xffffffff, v1, off);
                int   oj1 = __shfl_xor_sync(0xffffffff, j1, off);
                float ov2 = __shfl_xor_sync(0xffffffff, v2, off);
                int   oj2 = __shfl_xor_sync(0xffffffff, j2, off);
                float ov3 = __shfl_xor_sync(0xffffffff, v3, off);
                int   oj3 = __shfl_xor_sync(0xffffffff, j3, off);
                INS3(ov1, oj1);
                INS3(ov2, oj2);
                INS3(ov3, oj3);
            }
            if ((lane & 3) == 0) {
                int b = (wn * 128 + row) * 3;
                svv[b] = v1; svv[b + 1] = v2; svv[b + 2] = v3;
                sii[b] = j1; sii[b + 1] = j2; sii[b + 2] = j3;
            }
        }
    }
    __syncthreads();
    if (tid < 128) {
        int b0 = tid * 3, b1 = (128 + tid) * 3;
        float v1 = svv[b0], v2 = svv[b0 + 1], v3 = svv[b0 + 2];
        int   j1 = sii[b0], j2 = sii[b0 + 1], j3 = sii[b0 + 2];
        float w1 = svv[b1], w2 = svv[b1 + 1], w3 = svv[b1 + 2];
        int   k1 = sii[b1], k2 = sii[b1 + 1], k3 = sii[b1 + 2];
        INS3(w1, k1);
        INS3(w2, k2);
        INS3(w3, k3);
        size_t g = ((size_t)(row0 + tid) * 8 + nblk) * 3;
        g_cv[g] = v1; g_cv[g + 1] = v2; g_cv[g + 2] = v3;
        g_ci[g] = j1; g_ci[g + 1] = j2; g_ci[g + 2] = j3;
    }
}

// ---------------------------------------------------------------------------
// k_amin: reduce 24 candidates/row -> approx argmin; flag near-ties for refine
// ---------------------------------------------------------------------------
__global__ __launch_bounds__(256)
void k_amin() {
    int row = blockIdx.x * 256 + threadIdx.x;
    const float* cv = g_cv + (size_t)row * 24;
    const int*   ci = g_ci + (size_t)row * 24;
    float v1 = 3.4e38f, v2 = 3.4e38f;
    int i1 = 0x7fffffff;
#pragma unroll
    for (int k = 0; k < 24; ++k) {
        float v = cv[k];
        int   i = ci[k];
        if (v < v1 || (v == v1 && i < i1)) { v2 = v1; v1 = v; i1 = i; }
        else if (v < v2) v2 = v;
    }
    g_minidx[row] = i1;
    if (v2 - v1 <= WFLAG) {
        int p = atomicAdd(&g_count, 1);
        g_list[p] = row;
    }
}

// ---------------------------------------------------------------------------
// k_refine: exact fp32 dist for all within-window candidates of flagged rows
// ---------------------------------------------------------------------------
__global__ __launch_bounds__(128)
void k_refine(const float* __restrict__ z, const float* __restrict__ cb) {
    __shared__ float zrow[512];
    __shared__ float cdist[24];
    const int tid  = threadIdx.x;
    const int lane = tid & 31;
    const int w    = tid >> 5;
    const int cnt  = g_count;

    for (int b = blockIdx.x; b < cnt; b += gridDim.x) {
        __syncthreads();
        const int row = g_list[b];
        const int bi  = row >> 12;
        const int rem = row & 4095;
        for (int d = tid; d < 512; d += 128)
            zrow[d] = z[(size_t)bi * (DCH * HW) + (size_t)d * HW + rem];
        if (tid < 24) cdist[tid] = 3.4e38f;
        __syncthreads();

        const float* cv = g_cv + (size_t)row * 24;
        const int*   ci = g_ci + (size_t)row * 24;
        float v1 = 3.4e38f;
#pragma unroll
        for (int k = 0; k < 24; ++k) v1 = fminf(v1, cv[k]);
        const float zn = g_znorm[row];

        for (int c = w; c < 24; c += 4) {
            if (cv[c] <= v1 + WFLAG) {
                int idx = ci[c];
                const float* cr = cb + (size_t)idx * DCH;
                float dot = 0.f;
#pragma unroll
                for (int t = 0; t < 16; ++t)
                    dot = fmaf(zrow[lane + 32 * t], cr[lane + 32 * t], dot);
#pragma unroll
                for (int off = 16; off > 0; off >>= 1)
                    dot += __shfl_xor_sync(0xffffffff, dot, off);
                if (lane == 0)
                    cdist[c] = __fadd_rn(__fadd_rn(zn, g_cnorm[idx]),
                                         __fmul_rn(-2.f, dot));
            }
        }
        __syncthreads();
        if (tid == 0) {
            float bv = 3.4e38f;
            int bidx = 0x7fffffff;
#pragma unroll
            for (int k = 0; k < 24; ++k) {
                if (cdist[k] < 3.3e38f) {
                    int ii = ci[k];
                    if (cdist[k] < bv || (cdist[k] == bv && ii < bidx)) {
                        bv = cdist[k]; bidx = ii;
                    }
                }
            }
            g_minidx[row] = bidx;
        }
    }
}

// ---------------------------------------------------------------------------
// k_pg: MERGED prob + gather. Blocks [0,16384) = softmax normalize (prob);
// blocks [16384, 24576) = gather z_q + loss partials. Independent work — the
// latency-bound gather blocks interleave with BW-bound prob blocks.
// ---------------------------------------------------------------------------
__global__ __launch_bounds__(256)
void k_pg(float* __restrict__ prob,
          const float* __restrict__ z,
          const float* __restrict__ cb,
          float* __restrict__ outzq) {
    __shared__ float cbuf[128 * 33];     // gather; prob uses first 4*64 floats
    __shared__ int   s_idx[32];
    __shared__ float sred[256];
    const int tid = threadIdx.x;

    if (blockIdx.x < 16384) {
        // ---------------- prob ----------------
        float (*sval)[64] = (float (*)[64])cbuf;
        const int rg  = tid >> 6;
        const int cl  = tid & 63;
        const int row = (blockIdx.x << 2) + rg;
        const size_t base = ((size_t)row << 10) + cl;

        float s[16];
        float mv = 3.4e38f;
#pragma unroll
        for (int i = 0; i < 16; ++i) {
            s[i] = __half2float(g_sdist[base + 64 * i]);
            if (s[i] < mv) mv = s[i];
        }
        sval[rg][cl] = mv;
        __syncthreads();
        for (int off = 32; off > 0; off >>= 1) {
            if (cl < off) {
                float v2 = sval[rg][cl + off];
                if (v2 < sval[rg][cl]) sval[rg][cl] = v2;
            }
            __syncthreads();
        }
        float m = sval[rg][0];
        __syncthreads();

        float e[16], ssum = 0.f;
#pragma unroll
        for (int i = 0; i < 16; ++i) {
            e[i] = __expf(__fmul_rn(-2.f, __fsub_rn(s[i], m)));
            ssum += e[i];
        }
        sval[rg][cl] = ssum;
        __syncthreads();
        for (int off = 32; off > 0; off >>= 1) {
            if (cl < off) sval[rg][cl] += sval[rg][cl + off];
            __syncthreads();
        }
        float invS = 1.0f / sval[rg][0];
        float* op = prob + base;
#pragma unroll
        for (int i = 0; i < 16; ++i)
            op[64 * i] = e[i] * invS;
    } else {
        // ---------------- gather ----------------
        const int bid   = blockIdx.x - 16384;
        const int row0  = (bid >> 2) << 5;
        const int dbase = (bid & 3) << 7;
        const int bi    = row0 >> 12;
        const int rem0  = row0 & 4095;
        if (tid < 32) s_idx[tid] = g_minidx[row0 + tid];
        __syncthreads();

#pragma unroll
        for (int i = tid; i < 4096; i += 256) {
            int r = i >> 7, c = i & 127;
            cbuf[c * 33 + r] = cb[(size_t)s_idx[r] * DCH + dbase + c];
        }
        __syncthreads();

        float lsum = 0.f;
        const size_t zb = (size_t)bi * (DCH * HW) + rem0;
#pragma unroll
        for (int it = 0; it < 16; ++it) {
            int l    = tid + (it << 8);
            int rloc = l & 31;
            int dloc = l >> 5;
            size_t gi = zb + (size_t)(dbase + dloc) * HW + rloc;
            float c  = cbuf[dloc * 33 + rloc];
            float zv = z[gi];
            float df = c - zv;
            lsum += df * df;
            outzq[gi] = c;
        }
        sred[tid] = lsum;
        __syncthreads();
        for (int off = 128; off > 0; off >>= 1) {
            if (tid < off) sred[tid] += sred[tid + off];
            __syncthreads();
        }
        if (tid == 0) g_partial[bid] = sred[0];
    }
}

__global__ void k_loss(float* __restrict__ out) {
    __shared__ float s[1024];
    int tid = threadIdx.x;
    float a = 0.f;
#pragma unroll
    for (int i = 0; i < 8; ++i) a += g_partial[tid + 1024 * i];
    s[tid] = a;
    __syncthreads();
    for (int off = 512; off > 0; off >>= 1) {
        if (tid < off) s[tid] += s[tid + off];
        __syncthreads();
    }
    if (tid == 0) out[0] = s[0] * (1.25f / 33554432.f);
}

// ---------------------------------------------------------------------------
extern "C" void kernel_launch(void* const* d_in, const int* in_sizes, int n_in,
                              void* d_out, int out_size) {
    const float* z  = (const float*)d_in[0];
    const float* cb = (const float*)d_in[1];
    float* out = (float*)d_out;

    cudaFuncSetAttribute(k_gemm, cudaFuncAttributeMaxDynamicSharedMemorySize, GEMM_SMEM);

    k_csplit<<<1024, 256>>>(cb);
    k_zsplit<<<1024, 256>>>(z);
    k_gemm<<<4096, 256, GEMM_SMEM>>>();
    k_amin<<<256, 256>>>();
    k_refine<<<2048, 128>>>(z, cb);
    k_pg<<<24576, 256>>>(out + PROB_OFF, z, cb, out);
    k_loss<<<1, 1024>>>(out + LOSS_OFF);
}

// round 15
// speedup vs baseline: 1.0303x; 1.0091x over previous
#include <cuda_runtime.h>
#include <cuda_fp16.h>
#include <cstdint>

#define DCH   512
#define HW    4096
#define NROWS 65536
#define KCB   1024
#define LOSS_OFF 33554432
#define PROB_OFF 33554433
#define WFLAG 1.5e-4f

// ---------------- device scratch ----------------
__device__ float g_cnorm[KCB];
__device__ float g_znorm[NROWS];
__device__ int   g_minidx[NROWS];
__device__ float g_partial[8192];
__device__ __half g_zhi[(size_t)NROWS * DCH];
__device__ __half g_zlo[(size_t)NROWS * DCH];
__device__ __half g_chi[(size_t)KCB * DCH];
__device__ __half g_sdist[(size_t)NROWS * KCB];   // approx dist - znorm, fp16
__device__ float g_cv[(size_t)NROWS * 24];        // per-nblk top-3 approx dist
__device__ int   g_ci[(size_t)NROWS * 24];        // matching code indices
__device__ int   g_list[NROWS];
__device__ int   g_count;

// ---------------- PTX helpers ----------------
__device__ __forceinline__ uint32_t smem_u32(const void* p) {
    uint32_t a;
    asm("{ .reg .u64 t; cvta.to.shared.u64 t, %1; cvt.u32.u64 %0, t; }" : "=r"(a) : "l"(p));
    return a;
}
__device__ __forceinline__ void cpasync16(uint32_t s, const void* g) {
    asm volatile("cp.async.cg.shared.global [%0], [%1], 16;" :: "r"(s), "l"(g));
}
#define CP_COMMIT()  asm volatile("cp.async.commit_group;" ::: "memory")
#define CP_WAIT0()   asm volatile("cp.async.wait_group 0;" ::: "memory")

#define LDSM_X4(r0, r1, r2, r3, addr)                                          \
    asm volatile("ldmatrix.sync.aligned.m8n8.x4.shared.b16 {%0,%1,%2,%3}, [%4];" \
                 : "=r"(r0), "=r"(r1), "=r"(r2), "=r"(r3) : "r"(addr))

// non-volatile: ptxas may software-pipeline
#define MMA16816(d, a0, a1, a2, a3, b0, b1)                                    \
    asm("mma.sync.aligned.m16n8k16.row.col.f32.f16.f16.f32 "                   \
        "{%0,%1,%2,%3}, {%4,%5,%6,%7}, {%8,%9}, {%0,%1,%2,%3};"                \
        : "+f"((d)[0]), "+f"((d)[1]), "+f"((d)[2]), "+f"((d)[3])               \
        : "r"(a0), "r"(a1), "r"(a2), "r"(a3), "r"(b0), "r"(b1))

// lexicographic top-3 insert on (v1,j1,v2,j2,v3,j3)
#define INS3(dv, ji) do {                                                      \
    if ((dv) < v1 || ((dv) == v1 && (ji) < j1)) {                              \
        v3 = v2; j3 = j2; v2 = v1; j2 = j1; v1 = (dv); j1 = (ji);              \
    } else if ((dv) < v2 || ((dv) == v2 && (ji) < j2)) {                       \
        v3 = v2; j3 = j2; v2 = (dv); j2 = (ji);                                \
    } else if ((dv) < v3 || ((dv) == v3 && (ji) < j3)) {                       \
        v3 = (dv); j3 = (ji);                                                  \
    }                                                                          \
} while (0)

// ---------------------------------------------------------------------------
// codebook fp16 (hi only) + fused cnorm (sequential fp32) + counter zero
// ---------------------------------------------------------------------------
__global__ void k_csplit(const float* __restrict__ cb) {
    int idx = blockIdx.x * blockDim.x + threadIdx.x;
    if (idx == 0) g_count = 0;
    if (idx < (KCB * DCH) / 2) {
        float2 v = ((const float2*)cb)[idx];
        ((__half2*)g_chi)[idx] = __floats2half2_rn(v.x, v.y);
    }
    if (blockIdx.x < 4) {
        int jj = blockIdx.x * 256 + threadIdx.x;
        const float* r = cb + (size_t)jj * DCH;
        float acc = 0.f;
        for (int k = 0; k < DCH; ++k) {
            float v = r[k];
            acc = __fadd_rn(acc, __fmul_rn(v, v));
        }
        g_cnorm[jj] = acc;
    }
}

// ---------------------------------------------------------------------------
// z fp16 hi/lo split + fused znorm (exact sequential d-order per row)
// ---------------------------------------------------------------------------
__global__ __launch_bounds__(256)
void k_zsplit(const float* __restrict__ z) {
    __shared__ float sm[64 * 65];
    const int tid  = threadIdx.x;
    const int bi   = blockIdx.x >> 6;
    const int rem0 = (blockIdx.x & 63) << 6;
    const float* zb = z + (size_t)bi * (DCH * HW) + rem0;
    float zacc = 0.f;

    for (int kt = 0; kt < 8; ++kt) {
        __syncthreads();
        int k0 = kt * 64;
#pragma unroll
        for (int it = 0; it < 16; ++it) {
            int li = it * 256 + tid;
            int r = li & 63, k = li >> 6;
            sm[k * 65 + r] = zb[(size_t)(k0 + k) * HW + r];
        }
        __syncthreads();
        if (tid < 64) {
#pragma unroll 8
            for (int k = 0; k < 64; ++k) {
                float v = sm[k * 65 + tid];
                zacc = __fadd_rn(zacc, __fmul_rn(v, v));
            }
        }
        int r  = tid >> 2;
        int kq = tid & 3;
        uint32_t hbuf[8], lbuf[8];
#pragma unroll
        for (int i = 0; i < 8; ++i) {
            float v0 = sm[(kq * 16 + 2 * i)     * 65 + r];
            float v1 = sm[(kq * 16 + 2 * i + 1) * 65 + r];
            __half2 h = __floats2half2_rn(v0, v1);
            float h0 = __half2float(__low2half(h));
            float h1 = __half2float(__high2half(h));
            __half2 l = __floats2half2_rn(v0 - h0, v1 - h1);
            hbuf[i] = *(uint32_t*)&h;
            lbuf[i] = *(uint32_t*)&l;
        }
        size_t base = ((size_t)(bi * 4096 + rem0 + r)) * DCH + k0 + kq * 16;
        *(uint4*)((char*)g_zhi + base * 2)      = *(uint4*)(hbuf);
        *(uint4*)((char*)g_zhi + base * 2 + 16) = *(uint4*)(hbuf + 4);
        *(uint4*)((char*)g_zlo + base * 2)      = *(uint4*)(lbuf);
        *(uint4*)((char*)g_zlo + base * 2 + 16) = *(uint4*)(lbuf + 4);
    }
    if (tid < 64) g_znorm[bi * 4096 + rem0 + tid] = zacc;
}

// ---------------------------------------------------------------------------
// HMMA GEMM (round-10 proven config): fp16 2-product split, CTA 128x128,
// K-chunk 32, double buffer, 2 CTAs/SM, one barrier per k-chunk.
// Epilogue: per-nblk top-3 exact-fp32 candidates + fp16 (dist - zn) store.
// ---------------------------------------------------------------------------
#define PITCH 80
#define T_A_HI 0
#define T_A_LO 10240
#define T_B_HI 20480
#define STAGE_BYTES 30720
#define S_CN  61440
#define S_ZN  61952
#define S_CV  62464
#define S_CI  65536
#define GEMM_SMEM 68608

__global__ __launch_bounds__(256, 2)
void k_gemm() {
    extern __shared__ char smem[];
    const uint32_t sb = smem_u32(smem);
    const int tid   = threadIdx.x;
    const int lane  = tid & 31;
    const int wid   = tid >> 5;
    const int wm    = wid & 3;
    const int wn    = wid >> 2;
    const int rowblk = blockIdx.x >> 3;
    const int nblk   = blockIdx.x & 7;
    const int row0   = rowblk << 7;
    const int n0     = nblk << 7;

    const int srow = tid >> 2;
    const int sch  = tid & 3;

    const char* gAh = (const char*)g_zhi + ((size_t)(row0 + srow) << 10) + sch * 16;
    const char* gAl = (const char*)g_zlo + ((size_t)(row0 + srow) << 10) + sch * 16;
    const char* gBh = (const char*)g_chi + ((size_t)(n0   + srow) << 10) + sch * 16;
    const uint32_t sOff = srow * PITCH + sch * 16;

#define LOAD_STAGE(stg, kc) do {                                               \
    uint32_t s0 = sb + (stg) * STAGE_BYTES + sOff;                             \
    size_t   go = (size_t)(kc) * 64;                                           \
    cpasync16(s0 + T_A_HI,              gAh + go);                             \
    cpasync16(s0 + T_A_HI + 64 * PITCH, gAh + go + (size_t)64 * 1024);         \
    cpasync16(s0 + T_A_LO,              gAl + go);                             \
    cpasync16(s0 + T_A_LO + 64 * PITCH, gAl + go + (size_t)64 * 1024);         \
    cpasync16(s0 + T_B_HI,              gBh + go);                             \
    cpasync16(s0 + T_B_HI + 64 * PITCH, gBh + go + (size_t)64 * 1024);         \
    CP_COMMIT();                                                               \
} while (0)

    LOAD_STAGE(0, 0);

    float* s_cn = (float*)(smem + S_CN);
    float* s_zn = (float*)(smem + S_ZN);
    if (tid < 128) {
        s_cn[tid] = g_cnorm[n0 + tid];
        s_zn[tid] = g_znorm[row0 + tid];
    }

    float acc[2][8][4];
#pragma unroll
    for (int mi = 0; mi < 2; ++mi)
#pragma unroll
        for (int n8 = 0; n8 < 8; ++n8)
#pragma unroll
            for (int e = 0; e < 4; ++e) acc[mi][n8][e] = 0.f;

    const int aRow = (lane & 15);
    const int aChk = (lane >> 4);
    const int bRow = (lane & 7) + ((lane >> 4) << 3);
    const int bChk = ((lane >> 3) & 1);

    for (int kc = 0; kc < 16; ++kc) {
        CP_WAIT0();
        __syncthreads();
        if (kc + 1 < 16) LOAD_STAGE((kc + 1) & 1, kc + 1);

        const uint32_t st = sb + (kc & 1) * STAGE_BYTES;
#pragma unroll
        for (int ks = 0; ks < 2; ++ks) {
            uint32_t ah[2][4], al[2][4];
#pragma unroll
            for (int mi = 0; mi < 2; ++mi) {
                uint32_t ad = st + (wm * 32 + mi * 16 + aRow) * PITCH
                            + (ks * 2 + aChk) * 16;
                LDSM_X4(ah[mi][0], ah[mi][1], ah[mi][2], ah[mi][3], ad + T_A_HI);
                LDSM_X4(al[mi][0], al[mi][1], al[mi][2], al[mi][3], ad + T_A_LO);
            }
#pragma unroll
            for (int gp = 0; gp < 2; ++gp) {
                const int g0 = 2 * gp, g1 = 2 * gp + 1;
                uint32_t b0h[4], b1h[4];
                uint32_t bd0 = st + (wn * 64 + g0 * 16 + bRow) * PITCH
                             + (ks * 2 + bChk) * 16 + T_B_HI;
                uint32_t bd1 = st + (wn * 64 + g1 * 16 + bRow) * PITCH
                             + (ks * 2 + bChk) * 16 + T_B_HI;
                LDSM_X4(b0h[0], b0h[1], b0h[2], b0h[3], bd0);
                LDSM_X4(b1h[0], b1h[1], b1h[2], b1h[3], bd1);

                // term hh (8 distinct accumulators)
                MMA16816(acc[0][2*g0],   ah[0][0],ah[0][1],ah[0][2],ah[0][3], b0h[0], b0h[1]);
                MMA16816(acc[0][2*g0+1], ah[0][0],ah[0][1],ah[0][2],ah[0][3], b0h[2], b0h[3]);
                MMA16816(acc[1][2*g0],   ah[1][0],ah[1][1],ah[1][2],ah[1][3], b0h[0], b0h[1]);
                MMA16816(acc[1][2*g0+1], ah[1][0],ah[1][1],ah[1][2],ah[1][3], b0h[2], b0h[3]);
                MMA16816(acc[0][2*g1],   ah[0][0],ah[0][1],ah[0][2],ah[0][3], b1h[0], b1h[1]);
                MMA16816(acc[0][2*g1+1], ah[0][0],ah[0][1],ah[0][2],ah[0][3], b1h[2], b1h[3]);
                MMA16816(acc[1][2*g1],   ah[1][0],ah[1][1],ah[1][2],ah[1][3], b1h[0], b1h[1]);
                MMA16816(acc[1][2*g1+1], ah[1][0],ah[1][1],ah[1][2],ah[1][3], b1h[2], b1h[3]);
                // term lh (same B fragments)
                MMA16816(acc[0][2*g0],   al[0][0],al[0][1],al[0][2],al[0][3], b0h[0], b0h[1]);
                MMA16816(acc[0][2*g0+1], al[0][0],al[0][1],al[0][2],al[0][3], b0h[2], b0h[3]);
                MMA16816(acc[1][2*g0],   al[1][0],al[1][1],al[1][2],al[1][3], b0h[0], b0h[1]);
                MMA16816(acc[1][2*g0+1], al[1][0],al[1][1],al[1][2],al[1][3], b0h[2], b0h[3]);
                MMA16816(acc[0][2*g1],   al[0][0],al[0][1],al[0][2],al[0][3], b1h[0], b1h[1]);
                MMA16816(acc[0][2*g1+1], al[0][0],al[0][1],al[0][2],al[0][3], b1h[2], b1h[3]);
                MMA16816(acc[1][2*g1],   al[1][0],al[1][1],al[1][2],al[1][3], b1h[0], b1h[1]);
                MMA16816(acc[1][2*g1+1], al[1][0],al[1][1],al[1][2],al[1][3], b1h[2], b1h[3]);
            }
        }
    }
#undef LOAD_STAGE

    // epilogue: exact fp32 dist -> top-3 candidates; fp16 (dist - zn) store
    float* svv = (float*)(smem + S_CV);
    int*   sii = (int*)(smem + S_CI);
#pragma unroll
    for (int mi = 0; mi < 2; ++mi) {
        const int rbase = wm * 32 + mi * 16 + (lane >> 2);
#pragma unroll
        for (int h = 0; h < 2; ++h) {
            const int row = rbase + 8 * h;
            const float zn = s_zn[row];
            float v1 = 3.4e38f, v2 = 3.4e38f, v3 = 3.4e38f;
            int   j1 = 0x7fffffff, j2 = 0x7fffffff, j3 = 0x7fffffff;
#pragma unroll
            for (int n8 = 0; n8 < 8; ++n8) {
                int cloc = wn * 64 + n8 * 8 + (lane & 3) * 2;
                float cn0 = s_cn[cloc], cn1 = s_cn[cloc + 1];
                float* a = acc[mi][n8];
                float d0 = __fadd_rn(__fadd_rn(zn, cn0), __fmul_rn(-2.f, a[2 * h]));
                float d1 = __fadd_rn(__fadd_rn(zn, cn1), __fmul_rn(-2.f, a[2 * h + 1]));
                int j = n0 + cloc;
                INS3(d0, j);
                INS3(d1, j + 1);
                __half2 hs = __floats2half2_rn(d0 - zn, d1 - zn);
                *(__half2*)((char*)g_sdist + (((size_t)(row0 + row) << 10) + j) * 2) = hs;
            }
#pragma unroll
            for (int off = 1; off <= 2; off <<= 1) {
                float ov1 = __shfl_xor_sync(0xffffffff, v1, off);
                int   oj1 = __shfl_xor_sync(0xffffffff, j1, off);
                float ov2 = __shfl_xor_sync(0xffffffff, v2, off);
                int   oj2 = __shfl_xor_sync(0xffffffff, j2, off);
                float ov3 = __shfl_xor_sync(0xffffffff, v3, off);
                int   oj3 = __shfl_xor_sync(0xffffffff, j3, off);
                INS3(ov1, oj1);
                INS3(ov2, oj2);
                INS3(ov3, oj3);
            }
            if ((lane & 3) == 0) {
                int b = (wn * 128 + row) * 3;
                svv[b] = v1; svv[b + 1] = v2; svv[b + 2] = v3;
                sii[b] = j1; sii[b + 1] = j2; sii[b + 2] = j3;
            }
        }
    }
    __syncthreads();
    if (tid < 128) {
        int b0 = tid * 3, b1 = (128 + tid) * 3;
        float v1 = svv[b0], v2 = svv[b0 + 1], v3 = svv[b0 + 2];
        int   j1 = sii[b0], j2 = sii[b0 + 1], j3 = sii[b0 + 2];
        float w1 = svv[b1], w2 = svv[b1 + 1], w3 = svv[b1 + 2];
        int   k1 = sii[b1], k2 = sii[b1 + 1], k3 = sii[b1 + 2];
        INS3(w1, k1);
        INS3(w2, k2);
        INS3(w3, k3);
        size_t g = ((size_t)(row0 + tid) * 8 + nblk) * 3;
        g_cv[g] = v1; g_cv[g + 1] = v2; g_cv[g + 2] = v3;
        g_ci[g] = j1; g_ci[g + 1] = j2; g_ci[g + 2] = j3;
    }
}

// ---------------------------------------------------------------------------
// k_amin: reduce 24 candidates/row (vectorized float4/int4 loads) ->
// approx argmin; flag near-ties for refine
// ---------------------------------------------------------------------------
__global__ __launch_bounds__(256)
void k_amin() {
    int row = blockIdx.x * 256 + threadIdx.x;
    const float4* cv4 = (const float4*)(g_cv + (size_t)row * 24);
    const int4*   ci4 = (const int4*)(g_ci + (size_t)row * 24);
    float v1 = 3.4e38f, v2 = 3.4e38f;
    int i1 = 0x7fffffff;
#pragma unroll
    for (int k = 0; k < 6; ++k) {
        float4 v = cv4[k];
        int4   w = ci4[k];
        if (v.x < v1 || (v.x == v1 && w.x < i1)) { v2 = v1; v1 = v.x; i1 = w.x; }
        else if (v.x < v2) v2 = v.x;
        if (v.y < v1 || (v.y == v1 && w.y < i1)) { v2 = v1; v1 = v.y; i1 = w.y; }
        else if (v.y < v2) v2 = v.y;
        if (v.z < v1 || (v.z == v1 && w.z < i1)) { v2 = v1; v1 = v.z; i1 = w.z; }
        else if (v.z < v2) v2 = v.z;
        if (v.w < v1 || (v.w == v1 && w.w < i1)) { v2 = v1; v1 = v.w; i1 = w.w; }
        else if (v.w < v2) v2 = v.w;
    }
    g_minidx[row] = i1;
    if (v2 - v1 <= WFLAG) {
        int p = atomicAdd(&g_count, 1);
        g_list[p] = row;
    }
}

// ---------------------------------------------------------------------------
// k_refine: exact fp32 dist for all within-window candidates of flagged rows
// ---------------------------------------------------------------------------
__global__ __launch_bounds__(128)
void k_refine(const float* __restrict__ z, const float* __restrict__ cb) {
    __shared__ float zrow[512];
    __shared__ float cdist[24];
    const int tid  = threadIdx.x;
    const int lane = tid & 31;
    const int w    = tid >> 5;
    const int cnt  = g_count;

    for (int b = blockIdx.x; b < cnt; b += gridDim.x) {
        __syncthreads();
        const int row = g_list[b];
        const int bi  = row >> 12;
        const int rem = row & 4095;
        for (int d = tid; d < 512; d += 128)
            zrow[d] = z[(size_t)bi * (DCH * HW) + (size_t)d * HW + rem];
        if (tid < 24) cdist[tid] = 3.4e38f;
        __syncthreads();

        const float* cv = g_cv + (size_t)row * 24;
        const int*   ci = g_ci + (size_t)row * 24;
        float v1 = 3.4e38f;
#pragma unroll
        for (int k = 0; k < 24; ++k) v1 = fminf(v1, cv[k]);
        const float zn = g_znorm[row];

        for (int c = w; c < 24; c += 4) {
            if (cv[c] <= v1 + WFLAG) {
                int idx = ci[c];
                const float* cr = cb + (size_t)idx * DCH;
                float dot = 0.f;
#pragma unroll
                for (int t = 0; t < 16; ++t)
                    dot = fmaf(zrow[lane + 32 * t], cr[lane + 32 * t], dot);
#pragma unroll
                for (int off = 16; off > 0; off >>= 1)
                    dot += __shfl_xor_sync(0xffffffff, dot, off);
                if (lane == 0)
                    cdist[c] = __fadd_rn(__fadd_rn(zn, g_cnorm[idx]),
                                         __fmul_rn(-2.f, dot));
            }
        }
        __syncthreads();
        if (tid == 0) {
            float bv = 3.4e38f;
            int bidx = 0x7fffffff;
#pragma unroll
            for (int k = 0; k < 24; ++k) {
                if (cdist[k] < 3.3e38f) {
                    int ii = ci[k];
                    if (cdist[k] < bv || (cdist[k] == bv && ii < bidx)) {
                        bv = cdist[k]; bidx = ii;
                    }
                }
            }
            g_minidx[row] = bidx;
        }
    }
}

// ---------------------------------------------------------------------------
// k_pg: MERGED prob + gather. Blocks [0,16384) = shift-free softmax (prob,
// exp arg bounded so no max-subtract needed; softmax is shift-invariant);
// blocks [16384, 24576) = gather z_q + loss partials.
// ---------------------------------------------------------------------------
__global__ __launch_bounds__(256)
void k_pg(float* __restrict__ prob,
          const float* __restrict__ z,
          const float* __restrict__ cb,
          float* __restrict__ outzq) {
    __shared__ float cbuf[128 * 33];
    __shared__ int   s_idx[32];
    __shared__ float sred[256];
    const int tid = threadIdx.x;

    if (blockIdx.x < 16384) {
        // ---------------- prob (shift-free, 1 barrier) ----------------
        float* wsum = cbuf;              // 8 floats
        const int rg  = tid >> 6;
        const int cl  = tid & 63;
        const int row = (blockIdx.x << 2) + rg;
        const size_t base = ((size_t)row << 10) + cl;

        float e[16], ssum = 0.f;
#pragma unroll
        for (int i = 0; i < 16; ++i) {
            float s = __half2float(g_sdist[base + 64 * i]);
            e[i] = __expf(__fmul_rn(-2.f, s));
            ssum += e[i];
        }
        // warp-level sum (each row group = 2 warps)
#pragma unroll
        for (int off = 16; off > 0; off >>= 1)
            ssum += __shfl_xor_sync(0xffffffff, ssum, off);
        if ((tid & 31) == 0) wsum[tid >> 5] = ssum;
        __syncthreads();
        float tot = wsum[rg << 1] + wsum[(rg << 1) + 1];
        float invS = 1.0f / tot;

        float* op = prob + base;
#pragma unroll
        for (int i = 0; i < 16; ++i)
            op[64 * i] = e[i] * invS;
    } else {
        // ---------------- gather ----------------
        const int bid   = blockIdx.x - 16384;
        const int row0  = (bid >> 2) << 5;
        const int dbase = (bid & 3) << 7;
        const int bi    = row0 >> 12;
        const int rem0  = row0 & 4095;
        if (tid < 32) s_idx[tid] = g_minidx[row0 + tid];
        __syncthreads();

#pragma unroll
        for (int i = tid; i < 4096; i += 256) {
            int r = i >> 7, c = i & 127;
            cbuf[c * 33 + r] = cb[(size_t)s_idx[r] * DCH + dbase + c];
        }
        __syncthreads();

        float lsum = 0.f;
        const size_t zb = (size_t)bi * (DCH * HW) + rem0;
#pragma unroll
        for (int it = 0; it < 16; ++it) {
            int l    = tid + (it << 8);
            int rloc = l & 31;
            int dloc = l >> 5;
            size_t gi = zb + (size_t)(dbase + dloc) * HW + rloc;
            float c  = cbuf[dloc * 33 + rloc];
            float zv = z[gi];
            float df = c - zv;
            lsum += df * df;
            outzq[gi] = c;
        }
        sred[tid] = lsum;
        __syncthreads();
        for (int off = 128; off > 0; off >>= 1) {
            if (tid < off) sred[tid] += sred[tid + off];
            __syncthreads();
        }
        if (tid == 0) g_partial[bid] = sred[0];
    }
}

__global__ void k_loss(float* __restrict__ out) {
    __shared__ float s[1024];
    int tid = threadIdx.x;
    float a = 0.f;
#pragma unroll
    for (int i = 0; i < 8; ++i) a += g_partial[tid + 1024 * i];
    s[tid] = a;
    __syncthreads();
    for (int off = 512; off > 0; off >>= 1) {
        if (tid < off) s[tid] += s[tid + off];
        __syncthreads();
    }
    if (tid == 0) out[0] = s[0] * (1.25f / 33554432.f);
}

// ---------------------------------------------------------------------------
extern "C" void kernel_launch(void* const* d_in, const int* in_sizes, int n_in,
                              void* d_out, int out_size) {
    const float* z  = (const float*)d_in[0];
    const float* cb = (const float*)d_in[1];
    float* out = (float*)d_out;

    cudaFuncSetAttribute(k_gemm, cudaFuncAttributeMaxDynamicSharedMemorySize, GEMM_SMEM);

    k_csplit<<<1024, 256>>>(cb);
    k_zsplit<<<1024, 256>>>(z);
    k_gemm<<<4096, 256, GEMM_SMEM>>>();
    k_amin<<<256, 256>>>();
    k_refine<<<2048, 128>>>(z, cb);
    k_pg<<<24576, 256>>>(out + PROB_OFF, z, cb, out);
    k_loss<<<1, 1024>>>(out + LOSS_OFF);
}

// round 17
// speedup vs baseline: 1.0588x; 1.0276x over previous
#include <cuda_runtime.h>
#include <cuda_fp16.h>
#include <cstdint>

#define DCH   512
#define HW    4096
#define NROWS 65536
#define KCB   1024
#define LOSS_OFF 33554432
#define PROB_OFF 33554433
#define WFLAG 1.5e-4f

// ---------------- device scratch ----------------
__device__ float g_cnorm[KCB];
__device__ float g_znorm[NROWS];
__device__ int   g_minidx[NROWS];
__device__ float g_partial[8192];
__device__ __half g_zhi[(size_t)NROWS * DCH];
__device__ __half g_zlo[(size_t)NROWS * DCH];
__device__ __half g_chi[(size_t)KCB * DCH];
__device__ __half g_sdist[(size_t)NROWS * KCB];   // approx dist - znorm, fp16
__device__ float g_cv[(size_t)NROWS * 24];        // per-nblk top-3 approx dist
__device__ int   g_ci[(size_t)NROWS * 24];        // matching code indices
__device__ int   g_list[NROWS];
__device__ int   g_count;

// ---------------- PTX helpers ----------------
__device__ __forceinline__ uint32_t smem_u32(const void* p) {
    uint32_t a;
    asm("{ .reg .u64 t; cvta.to.shared.u64 t, %1; cvt.u32.u64 %0, t; }" : "=r"(a) : "l"(p));
    return a;
}
__device__ __forceinline__ void cpasync16(uint32_t s, const void* g) {
    asm volatile("cp.async.cg.shared.global [%0], [%1], 16;" :: "r"(s), "l"(g));
}
#define CP_COMMIT()  asm volatile("cp.async.commit_group;" ::: "memory")
#define CP_WAIT0()   asm volatile("cp.async.wait_group 0;" ::: "memory")

#define LDSM_X4(r0, r1, r2, r3, addr)                                          \
    asm volatile("ldmatrix.sync.aligned.m8n8.x4.shared.b16 {%0,%1,%2,%3}, [%4];" \
                 : "=r"(r0), "=r"(r1), "=r"(r2), "=r"(r3) : "r"(addr))

// non-volatile: ptxas may software-pipeline
#define MMA16816(d, a0, a1, a2, a3, b0, b1)                                    \
    asm("mma.sync.aligned.m16n8k16.row.col.f32.f16.f16.f32 "                   \
        "{%0,%1,%2,%3}, {%4,%5,%6,%7}, {%8,%9}, {%0,%1,%2,%3};"                \
        : "+f"((d)[0]), "+f"((d)[1]), "+f"((d)[2]), "+f"((d)[3])               \
        : "r"(a0), "r"(a1), "r"(a2), "r"(a3), "r"(b0), "r"(b1))

// lexicographic top-3 insert on (v1,j1,v2,j2,v3,j3)
#define INS3(dv, ji) do {                                                      \
    if ((dv) < v1 || ((dv) == v1 && (ji) < j1)) {                              \
        v3 = v2; j3 = j2; v2 = v1; j2 = j1; v1 = (dv); j1 = (ji);              \
    } else if ((dv) < v2 || ((dv) == v2 && (ji) < j2)) {                       \
        v3 = v2; j3 = j2; v2 = (dv); j2 = (ji);                                \
    } else if ((dv) < v3 || ((dv) == v3 && (ji) < j3)) {                       \
        v3 = (dv); j3 = (ji);                                                  \
    }                                                                          \
} while (0)

// ---------------------------------------------------------------------------
// k_split (MERGED): blocks [0,1024) = z fp16 hi/lo split + fused znorm;
// blocks [1024,2048) = codebook fp16 + fused cnorm + counter zero.
// ---------------------------------------------------------------------------
__global__ __launch_bounds__(256)
void k_split(const float* __restrict__ z, const float* __restrict__ cb) {
    __shared__ float sm[64 * 65];
    const int tid = threadIdx.x;

    if (blockIdx.x >= 1024) {
        // ---------------- csplit + cnorm ----------------
        const int cid = blockIdx.x - 1024;
        int idx = cid * 256 + tid;
        if (idx == 0) g_count = 0;
        float2 v = ((const float2*)cb)[idx];
        ((__half2*)g_chi)[idx] = __floats2half2_rn(v.x, v.y);
        if (cid < 4) {
            int jj = cid * 256 + tid;
            const float* r = cb + (size_t)jj * DCH;
            float acc = 0.f;
            for (int k = 0; k < DCH; ++k) {
                float vv = r[k];
                acc = __fadd_rn(acc, __fmul_rn(vv, vv));
            }
            g_cnorm[jj] = acc;
        }
        return;
    }

    // ---------------- zsplit + znorm ----------------
    const int bi   = blockIdx.x >> 6;
    const int rem0 = (blockIdx.x & 63) << 6;
    const float* zb = z + (size_t)bi * (DCH * HW) + rem0;
    float zacc = 0.f;

    for (int kt = 0; kt < 8; ++kt) {
        __syncthreads();
        int k0 = kt * 64;
#pragma unroll
        for (int it = 0; it < 16; ++it) {
            int li = it * 256 + tid;
            int r = li & 63, k = li >> 6;
            sm[k * 65 + r] = zb[(size_t)(k0 + k) * HW + r];
        }
        __syncthreads();
        if (tid < 64) {
#pragma unroll 8
            for (int k = 0; k < 64; ++k) {
                float v = sm[k * 65 + tid];
                zacc = __fadd_rn(zacc, __fmul_rn(v, v));
            }
        }
        int r  = tid >> 2;
        int kq = tid & 3;
        uint32_t hbuf[8], lbuf[8];
#pragma unroll
        for (int i = 0; i < 8; ++i) {
            float v0 = sm[(kq * 16 + 2 * i)     * 65 + r];
            float v1 = sm[(kq * 16 + 2 * i + 1) * 65 + r];
            __half2 h = __floats2half2_rn(v0, v1);
            float h0 = __half2float(__low2half(h));
            float h1 = __half2float(__high2half(h));
            __half2 l = __floats2half2_rn(v0 - h0, v1 - h1);
            hbuf[i] = *(uint32_t*)&h;
            lbuf[i] = *(uint32_t*)&l;
        }
        size_t base = ((size_t)(bi * 4096 + rem0 + r)) * DCH + k0 + kq * 16;
        *(uint4*)((char*)g_zhi + base * 2)      = *(uint4*)(hbuf);
        *(uint4*)((char*)g_zhi + base * 2 + 16) = *(uint4*)(hbuf + 4);
        *(uint4*)((char*)g_zlo + base * 2)      = *(uint4*)(lbuf);
        *(uint4*)((char*)g_zlo + base * 2 + 16) = *(uint4*)(lbuf + 4);
    }
    if (tid < 64) g_znorm[bi * 4096 + rem0 + tid] = zacc;
}

// ---------------------------------------------------------------------------
// HMMA GEMM (round-10 proven config): fp16 2-product split, CTA 128x128,
// K-chunk 32, double buffer, 2 CTAs/SM, one barrier per k-chunk.
// Epilogue: per-nblk top-3 exact-fp32 candidates + fp16 (dist - zn) store.
// ---------------------------------------------------------------------------
#define PITCH 80
#define T_A_HI 0
#define T_A_LO 10240
#define T_B_HI 20480
#define STAGE_BYTES 30720
#define S_CN  61440
#define S_ZN  61952
#define S_CV  62464
#define S_CI  65536
#define GEMM_SMEM 68608

__global__ __launch_bounds__(256, 2)
void k_gemm() {
    extern __shared__ char smem[];
    const uint32_t sb = smem_u32(smem);
    const int tid   = threadIdx.x;
    const int lane  = tid & 31;
    const int wid   = tid >> 5;
    const int wm    = wid & 3;
    const int wn    = wid >> 2;
    const int rowblk = blockIdx.x >> 3;
    const int nblk   = blockIdx.x & 7;
    const int row0   = rowblk << 7;
    const int n0     = nblk << 7;

    const int srow = tid >> 2;
    const int sch  = tid & 3;

    const char* gAh = (const char*)g_zhi + ((size_t)(row0 + srow) << 10) + sch * 16;
    const char* gAl = (const char*)g_zlo + ((size_t)(row0 + srow) << 10) + sch * 16;
    const char* gBh = (const char*)g_chi + ((size_t)(n0   + srow) << 10) + sch * 16;
    const uint32_t sOff = srow * PITCH + sch * 16;

#define LOAD_STAGE(stg, kc) do {                                               \
    uint32_t s0 = sb + (stg) * STAGE_BYTES + sOff;                             \
    size_t   go = (size_t)(kc) * 64;                                           \
    cpasync16(s0 + T_A_HI,              gAh + go);                             \
    cpasync16(s0 + T_A_HI + 64 * PITCH, gAh + go + (size_t)64 * 1024);         \
    cpasync16(s0 + T_A_LO,              gAl + go);                             \
    cpasync16(s0 + T_A_LO + 64 * PITCH, gAl + go + (size_t)64 * 1024);         \
    cpasync16(s0 + T_B_HI,              gBh + go);                             \
    cpasync16(s0 + T_B_HI + 64 * PITCH, gBh + go + (size_t)64 * 1024);         \
    CP_COMMIT();                                                               \
} while (0)

    LOAD_STAGE(0, 0);

    float* s_cn = (float*)(smem + S_CN);
    float* s_zn = (float*)(smem + S_ZN);
    if (tid < 128) {
        s_cn[tid] = g_cnorm[n0 + tid];
        s_zn[tid] = g_znorm[row0 + tid];
    }

    float acc[2][8][4];
#pragma unroll
    for (int mi = 0; mi < 2; ++mi)
#pragma unroll
        for (int n8 = 0; n8 < 8; ++n8)
#pragma unroll
            for (int e = 0; e < 4; ++e) acc[mi][n8][e] = 0.f;

    const int aRow = (lane & 15);
    const int aChk = (lane >> 4);
    const int bRow = (lane & 7) + ((lane >> 4) << 3);
    const int bChk = ((lane >> 3) & 1);

    for (int kc = 0; kc < 16; ++kc) {
        CP_WAIT0();
        __syncthreads();
        if (kc + 1 < 16) LOAD_STAGE((kc + 1) & 1, kc + 1);

        const uint32_t st = sb + (kc & 1) * STAGE_BYTES;
#pragma unroll
        for (int ks = 0; ks < 2; ++ks) {
            uint32_t ah[2][4], al[2][4];
#pragma unroll
            for (int mi = 0; mi < 2; ++mi) {
                uint32_t ad = st + (wm * 32 + mi * 16 + aRow) * PITCH
                            + (ks * 2 + aChk) * 16;
                LDSM_X4(ah[mi][0], ah[mi][1], ah[mi][2], ah[mi][3], ad + T_A_HI);
                LDSM_X4(al[mi][0], al[mi][1], al[mi][2], al[mi][3], ad + T_A_LO);
            }
#pragma unroll
            for (int gp = 0; gp < 2; ++gp) {
                const int g0 = 2 * gp, g1 = 2 * gp + 1;
                uint32_t b0h[4], b1h[4];
                uint32_t bd0 = st + (wn * 64 + g0 * 16 + bRow) * PITCH
                             + (ks * 2 + bChk) * 16 + T_B_HI;
                uint32_t bd1 = st + (wn * 64 + g1 * 16 + bRow) * PITCH
                             + (ks * 2 + bChk) * 16 + T_B_HI;
                LDSM_X4(b0h[0], b0h[1], b0h[2], b0h[3], bd0);
                LDSM_X4(b1h[0], b1h[1], b1h[2], b1h[3], bd1);

                // term hh (8 distinct accumulators)
                MMA16816(acc[0][2*g0],   ah[0][0],ah[0][1],ah[0][2],ah[0][3], b0h[0], b0h[1]);
                MMA16816(acc[0][2*g0+1], ah[0][0],ah[0][1],ah[0][2],ah[0][3], b0h[2], b0h[3]);
                MMA16816(acc[1][2*g0],   ah[1][0],ah[1][1],ah[1][2],ah[1][3], b0h[0], b0h[1]);
                MMA16816(acc[1][2*g0+1], ah[1][0],ah[1][1],ah[1][2],ah[1][3], b0h[2], b0h[3]);
                MMA16816(acc[0][2*g1],   ah[0][0],ah[0][1],ah[0][2],ah[0][3], b1h[0], b1h[1]);
                MMA16816(acc[0][2*g1+1], ah[0][0],ah[0][1],ah[0][2],ah[0][3], b1h[2], b1h[3]);
                MMA16816(acc[1][2*g1],   ah[1][0],ah[1][1],ah[1][2],ah[1][3], b1h[0], b1h[1]);
                MMA16816(acc[1][2*g1+1], ah[1][0],ah[1][1],ah[1][2],ah[1][3], b1h[2], b1h[3]);
                // term lh (same B fragments)
                MMA16816(acc[0][2*g0],   al[0][0],al[0][1],al[0][2],al[0][3], b0h[0], b0h[1]);
                MMA16816(acc[0][2*g0+1], al[0][0],al[0][1],al[0][2],al[0][3], b0h[2], b0h[3]);
                MMA16816(acc[1][2*g0],   al[1][0],al[1][1],al[1][2],al[1][3], b0h[0], b0h[1]);
                MMA16816(acc[1][2*g0+1], al[1][0],al[1][1],al[1][2],al[1][3], b0h[2], b0h[3]);
                MMA16816(acc[0][2*g1],   al[0][0],al[0][1],al[0][2],al[0][3], b1h[0], b1h[1]);
                MMA16816(acc[0][2*g1+1], al[0][0],al[0][1],al[0][2],al[0][3], b1h[2], b1h[3]);
                MMA16816(acc[1][2*g1],   al[1][0],al[1][1],al[1][2],al[1][3], b1h[0], b1h[1]);
                MMA16816(acc[1][2*g1+1], al[1][0],al[1][1],al[1][2],al[1][3], b1h[2], b1h[3]);
            }
        }
    }
#undef LOAD_STAGE

    // epilogue: exact fp32 dist -> top-3 candidates; fp16 (dist - zn) store
    float* svv = (float*)(smem + S_CV);
    int*   sii = (int*)(smem + S_CI);
#pragma unroll
    for (int mi = 0; mi < 2; ++mi) {
        const int rbase = wm * 32 + mi * 16 + (lane >> 2);
#pragma unroll
        for (int h = 0; h < 2; ++h) {
            const int row = rbase + 8 * h;
            const float zn = s_zn[row];
            float v1 = 3.4e38f, v2 = 3.4e38f, v3 = 3.4e38f;
            int   j1 = 0x7fffffff, j2 = 0x7fffffff, j3 = 0x7fffffff;
#pragma unroll
            for (int n8 = 0; n8 < 8; ++n8) {
                int cloc = wn * 64 + n8 * 8 + (lane & 3) * 2;
                float cn0 = s_cn[cloc], cn1 = s_cn[cloc + 1];
                float* a = acc[mi][n8];
                float d0 = __fadd_rn(__fadd_rn(zn, cn0), __fmul_rn(-2.f, a[2 * h]));
                float d1 = __fadd_rn(__fadd_rn(zn, cn1), __fmul_rn(-2.f, a[2 * h + 1]));
                int j = n0 + cloc;
                INS3(d0, j);
                INS3(d1, j + 1);
                __half2 hs = __floats2half2_rn(d0 - zn, d1 - zn);
                *(__half2*)((char*)g_sdist + (((size_t)(row0 + row) << 10) + j) * 2) = hs;
            }
#pragma unroll
            for (int off = 1; off <= 2; off <<= 1) {
                float ov1 = __shfl_xor_sync(0xffffffff, v1, off);
                int   oj1 = __shfl_xor_sync(0xffffffff, j1, off);
                float ov2 = __shfl_xor_sync(0xffffffff, v2, off);
                int   oj2 = __shfl_xor_sync(0xffffffff, j2, off);
                float ov3 = __shfl_xor_sync(0xffffffff, v3, off);
                int   oj3 = __shfl_xor_sync(0xffffffff, j3, off);
                INS3(ov1, oj1);
                INS3(ov2, oj2);
                INS3(ov3, oj3);
            }
            if ((lane & 3) == 0) {
                int b = (wn * 128 + row) * 3;
                svv[b] = v1; svv[b + 1] = v2; svv[b + 2] = v3;
                sii[b] = j1; sii[b + 1] = j2; sii[b + 2] = j3;
            }
        }
    }
    __syncthreads();
    if (tid < 128) {
        int b0 = tid * 3, b1 = (128 + tid) * 3;
        float v1 = svv[b0], v2 = svv[b0 + 1], v3 = svv[b0 + 2];
        int   j1 = sii[b0], j2 = sii[b0 + 1], j3 = sii[b0 + 2];
        float w1 = svv[b1], w2 = svv[b1 + 1], w3 = svv[b1 + 2];
        int   k1 = sii[b1], k2 = sii[b1 + 1], k3 = sii[b1 + 2];
        INS3(w1, k1);
        INS3(w2, k2);
        INS3(w3, k3);
        size_t g = ((size_t)(row0 + tid) * 8 + nblk) * 3;
        g_cv[g] = v1; g_cv[g + 1] = v2; g_cv[g + 2] = v3;
        g_ci[g] = j1; g_ci[g + 1] = j2; g_ci[g + 2] = j3;
    }
}

// ---------------------------------------------------------------------------
// k_amin: reduce 24 candidates/row (vectorized float4/int4 loads) ->
// approx argmin; flag near-ties for refine
// ---------------------------------------------------------------------------
__global__ __launch_bounds__(256)
void k_amin() {
    int row = blockIdx.x * 256 + threadIdx.x;
    const float4* cv4 = (const float4*)(g_cv + (size_t)row * 24);
    const int4*   ci4 = (const int4*)(g_ci + (size_t)row * 24);
    float v1 = 3.4e38f, v2 = 3.4e38f;
    int i1 = 0x7fffffff;
#pragma unroll
    for (int k = 0; k < 6; ++k) {
        float4 v = cv4[k];
        int4   w = ci4[k];
        if (v.x < v1 || (v.x == v1 && w.x < i1)) { v2 = v1; v1 = v.x; i1 = w.x; }
        else if (v.x < v2) v2 = v.x;
        if (v.y < v1 || (v.y == v1 && w.y < i1)) { v2 = v1; v1 = v.y; i1 = w.y; }
        else if (v.y < v2) v2 = v.y;
        if (v.z < v1 || (v.z == v1 && w.z < i1)) { v2 = v1; v1 = v.z; i1 = w.z; }
        else if (v.z < v2) v2 = v.z;
        if (v.w < v1 || (v.w == v1 && w.w < i1)) { v2 = v1; v1 = v.w; i1 = w.w; }
        else if (v.w < v2) v2 = v.w;
    }
    g_minidx[row] = i1;
    if (v2 - v1 <= WFLAG) {
        int p = atomicAdd(&g_count, 1);
        g_list[p] = row;
    }
}

// ---------------------------------------------------------------------------
// k_refine: exact fp32 dist for all within-window candidates of flagged rows
// ---------------------------------------------------------------------------
__global__ __launch_bounds__(128)
void k_refine(const float* __restrict__ z, const float* __restrict__ cb) {
    __shared__ float zrow[512];
    __shared__ float cdist[24];
    const int tid  = threadIdx.x;
    const int lane = tid & 31;
    const int w    = tid >> 5;
    const int cnt  = g_count;

    for (int b = blockIdx.x; b < cnt; b += gridDim.x) {
        __syncthreads();
        const int row = g_list[b];
        const int bi  = row >> 12;
        const int rem = row & 4095;
        for (int d = tid; d < 512; d += 128)
            zrow[d] = z[(size_t)bi * (DCH * HW) + (size_t)d * HW + rem];
        if (tid < 24) cdist[tid] = 3.4e38f;
        __syncthreads();

        const float* cv = g_cv + (size_t)row * 24;
        const int*   ci = g_ci + (size_t)row * 24;
        float v1 = 3.4e38f;
#pragma unroll
        for (int k = 0; k < 24; ++k) v1 = fminf(v1, cv[k]);
        const float zn = g_znorm[row];

        for (int c = w; c < 24; c += 4) {
            if (cv[c] <= v1 + WFLAG) {
                int idx = ci[c];
                const float* cr = cb + (size_t)idx * DCH;
                float dot = 0.f;
#pragma unroll
                for (int t = 0; t < 16; ++t)
                    dot = fmaf(zrow[lane + 32 * t], cr[lane + 32 * t], dot);
#pragma unroll
                for (int off = 16; off > 0; off >>= 1)
                    dot += __shfl_xor_sync(0xffffffff, dot, off);
                if (lane == 0)
                    cdist[c] = __fadd_rn(__fadd_rn(zn, g_cnorm[idx]),
                                         __fmul_rn(-2.f, dot));
            }
        }
        __syncthreads();
        if (tid == 0) {
            float bv = 3.4e38f;
            int bidx = 0x7fffffff;
#pragma unroll
            for (int k = 0; k < 24; ++k) {
                if (cdist[k] < 3.3e38f) {
                    int ii = ci[k];
                    if (cdist[k] < bv || (cdist[k] == bv && ii < bidx)) {
                        bv = cdist[k]; bidx = ii;
                    }
                }
            }
            g_minidx[row] = bidx;
        }
    }
}

// ---------------------------------------------------------------------------
// k_pg: MERGED prob + gather. Blocks [0,16384) = shift-free softmax with
// half2-vectorized LOADS and scalar float stores (prob pointer is only
// 4B-aligned: PROB_OFF is odd). Blocks [16384, 24576) = gather.
// ---------------------------------------------------------------------------
__global__ __launch_bounds__(256)
void k_pg(float* __restrict__ prob,
          const float* __restrict__ z,
          const float* __restrict__ cb,
          float* __restrict__ outzq) {
    __shared__ float cbuf[128 * 33];
    __shared__ int   s_idx[32];
    __shared__ float sred[256];
    const int tid = threadIdx.x;

    if (blockIdx.x < 16384) {
        // ------- prob (shift-free, half2 loads, scalar stores) -------
        float* wsum = cbuf;              // 8 floats
        const int rg  = tid >> 6;
        const int cl  = tid & 63;
        const int row = (blockIdx.x << 2) + rg;
        const size_t base2 = ((size_t)row << 10) + cl * 2;   // column pair base

        float2 e[8];
        float ssum = 0.f;
#pragma unroll
        for (int i = 0; i < 8; ++i) {
            __half2 hv = *(const __half2*)&g_sdist[base2 + 128 * i];
            float s0 = __half2float(__low2half(hv));
            float s1 = __half2float(__high2half(hv));
            e[i].x = __expf(__fmul_rn(-2.f, s0));
            e[i].y = __expf(__fmul_rn(-2.f, s1));
            ssum += e[i].x + e[i].y;
        }
#pragma unroll
        for (int off = 16; off > 0; off >>= 1)
            ssum += __shfl_xor_sync(0xffffffff, ssum, off);
        if ((tid & 31) == 0) wsum[tid >> 5] = ssum;
        __syncthreads();
        float tot = wsum[rg << 1] + wsum[(rg << 1) + 1];
        float invS = 1.0f / tot;

        float* op = prob + base2;
#pragma unroll
        for (int i = 0; i < 8; ++i) {
            op[128 * i]     = e[i].x * invS;
            op[128 * i + 1] = e[i].y * invS;
        }
    } else {
        // ---------------- gather ----------------
        const int bid   = blockIdx.x - 16384;
        const int row0  = (bid >> 2) << 5;
        const int dbase = (bid & 3) << 7;
        const int bi    = row0 >> 12;
        const int rem0  = row0 & 4095;
        if (tid < 32) s_idx[tid] = g_minidx[row0 + tid];
        __syncthreads();

#pragma unroll
        for (int i = tid; i < 4096; i += 256) {
            int r = i >> 7, c = i & 127;
            cbuf[c * 33 + r] = cb[(size_t)s_idx[r] * DCH + dbase + c];
        }
        __syncthreads();

        float lsum = 0.f;
        const size_t zb = (size_t)bi * (DCH * HW) + rem0;
#pragma unroll
        for (int it = 0; it < 16; ++it) {
            int l    = tid + (it << 8);
            int rloc = l & 31;
            int dloc = l >> 5;
            size_t gi = zb + (size_t)(dbase + dloc) * HW + rloc;
            float c  = cbuf[dloc * 33 + rloc];
            float zv = z[gi];
            float df = c - zv;
            lsum += df * df;
            outzq[gi] = c;
        }
        sred[tid] = lsum;
        __syncthreads();
        for (int off = 128; off > 0; off >>= 1) {
            if (tid < off) sred[tid] += sred[tid + off];
            __syncthreads();
        }
        if (tid == 0) g_partial[bid] = sred[0];
    }
}

__global__ void k_loss(float* __restrict__ out) {
    __shared__ float s[1024];
    int tid = threadIdx.x;
    float a = 0.f;
#pragma unroll
    for (int i = 0; i < 8; ++i) a += g_partial[tid + 1024 * i];
    s[tid] = a;
    __syncthreads();
    for (int off = 512; off > 0; off >>= 1) {
        if (tid < off) s[tid] += s[tid + off];
        __syncthreads();
    }
    if (tid == 0) out[0] = s[0] * (1.25f / 33554432.f);
}

// ---------------------------------------------------------------------------
extern "C" void kernel_launch(void* const* d_in, const int* in_sizes, int n_in,
                              void* d_out, int out_size) {
    const float* z  = (const float*)d_in[0];
    const float* cb = (const float*)d_in[1];
    float* out = (float*)d_out;

    cudaFuncSetAttribute(k_gemm, cudaFuncAttributeMaxDynamicSharedMemorySize, GEMM_SMEM);

    k_split<<<2048, 256>>>(z, cb);
    k_gemm<<<4096, 256, GEMM_SMEM>>>();
    k_amin<<<256, 256>>>();
    k_refine<<<2048, 128>>>(z, cb);
    k_pg<<<24576, 256>>>(out + PROB_OFF, z, cb, out);
    k_loss<<<1, 1024>>>(out + LOSS_OFF);
}